// round 3
// baseline (speedup 1.0000x reference)
#include <cuda_runtime.h>

#define BN 1024
#define TN 128
#define HN 128

// 64 MB scratch for the precomputed embedding (B*T*H floats) — __device__ global,
// no dynamic allocation.
__device__ float g_emb[BN * TN * HN];
// cos/sin of 0.5*theta for the variational weights: [gate(4)][layer(4)][qubit(8)]
__device__ float g_wc[128];
__device__ float g_ws[128];

// ---------------------------------------------------------------------------
// Kernel 1: precompute cos/sin of variational weight angles (accurate sincosf)
// ---------------------------------------------------------------------------
__global__ void k_sincos(const float* __restrict__ wi, const float* __restrict__ wf,
                         const float* __restrict__ wg, const float* __restrict__ wo) {
    int i = threadIdx.x;
    if (i < 128) {
        int gate = i >> 5, idx = i & 31;
        const float* w = (gate == 0) ? wi : (gate == 1) ? wf : (gate == 2) ? wg : wo;
        float s, c;
        sincosf(0.5f * w[idx], &s, &c);
        g_wc[i] = c;
        g_ws[i] = s;
    }
}

// ---------------------------------------------------------------------------
// Kernel 2: emb = LN(x @ emb_w.T + emb_b; g, bt) + pe[t]
// One warp per (b,t) row; 4 outputs per lane.
// ---------------------------------------------------------------------------
__global__ __launch_bounds__(256) void k_emb(
    const float* __restrict__ x, const float* __restrict__ pe,
    const float* __restrict__ ew, const float* __restrict__ eb,
    const float* __restrict__ eg, const float* __restrict__ ebt) {
    int warp = threadIdx.x >> 5, lane = threadIdx.x & 31;
    int row = blockIdx.x * 8 + warp;  // row in [0, B*T)
    if (row >= BN * TN) return;

    const float* xr = x + row * 8;
    float4 x0 = *(const float4*)xr;
    float4 x1 = *(const float4*)(xr + 4);

    float pre[4];
    float sum = 0.f, sq = 0.f;
#pragma unroll
    for (int m = 0; m < 4; m++) {
        int r = lane + 32 * m;
        const float4* wr = (const float4*)(ew + r * 8);
        float4 wa = wr[0], wb = wr[1];
        float a = eb[r];
        a = fmaf(x0.x, wa.x, a); a = fmaf(x0.y, wa.y, a);
        a = fmaf(x0.z, wa.z, a); a = fmaf(x0.w, wa.w, a);
        a = fmaf(x1.x, wb.x, a); a = fmaf(x1.y, wb.y, a);
        a = fmaf(x1.z, wb.z, a); a = fmaf(x1.w, wb.w, a);
        pre[m] = a;
        sum += a;
        sq = fmaf(a, a, sq);
    }
#pragma unroll
    for (int d = 16; d; d >>= 1) {
        sum += __shfl_xor_sync(0xffffffffu, sum, d);
        sq  += __shfl_xor_sync(0xffffffffu, sq, d);
    }
    float mean = sum * (1.f / 128.f);
    float var = sq * (1.f / 128.f) - mean * mean;
    float rstd = rsqrtf(var + 1e-5f);
    int t = row & (TN - 1);
#pragma unroll
    for (int m = 0; m < 4; m++) {
        int r = lane + 32 * m;
        g_emb[row * HN + r] = (pre[m] - mean) * rstd * eg[r] + ebt[r] + pe[t * HN + r];
    }
}

// ---------------------------------------------------------------------------
// VQC helpers. State: 256 real amplitudes per batch element, distributed as
// lane = amp[7:3], st[j] = amp with amp[2:0]==j.
// Qubit q acts on bit position (7-q). CNOT(c): ctrl bit 7-c, target bit 6-c.
// ---------------------------------------------------------------------------
template <int Q>
__device__ __forceinline__ void apply_ry(float (&st)[8], float cs, float sn, int lane) {
    if constexpr (Q <= 4) {
        constexpr int lb = 4 - Q;          // lane bit
        constexpr int mask = 1 << lb;      // shuffle partner
        float sg = ((lane >> lb) & 1) ? sn : -sn;
#pragma unroll
        for (int j = 0; j < 8; j++) {
            float o = __shfl_xor_sync(0xffffffffu, st[j], mask);
            st[j] = fmaf(sg, o, cs * st[j]);
        }
    } else {
        constexpr int step = 1 << (7 - Q); // intra-thread bit
#pragma unroll
        for (int j0 = 0; j0 < 8; j0++) {
            if ((j0 & step) == 0) {
                int j1 = j0 | step;
                float xx = st[j0], yy = st[j1];
                st[j0] = fmaf(-sn, yy, cs * xx);
                st[j1] = fmaf(sn, xx, cs * yy);
            }
        }
    }
}

__device__ __forceinline__ void cnot_lane(float (&st)[8], int lane, int cmask, int xmask) {
    bool hi = (lane & cmask) != 0;
#pragma unroll
    for (int j = 0; j < 8; j++) {
        float o = __shfl_xor_sync(0xffffffffu, st[j], xmask);
        st[j] = hi ? o : st[j];
    }
}

__device__ __forceinline__ void cnot_even(float (&st)[8], int lane) {
    cnot_lane(st, lane, 16, 8);  // c=0: ctrl bit7(lb4), tgt bit6(lb3)
    cnot_lane(st, lane, 4, 2);   // c=2: ctrl bit5(lb2), tgt bit4(lb1)
    {                            // c=4: ctrl bit3(lb0), tgt bit2 (intra)
        bool hi = (lane & 1) != 0;
#pragma unroll
        for (int j = 0; j < 4; j++) {
            float a = st[j], b = st[j + 4];
            st[j] = hi ? b : a;
            st[j + 4] = hi ? a : b;
        }
    }
    {                            // c=6: ctrl bit1, tgt bit0 (intra, free)
        float t1 = st[2]; st[2] = st[3]; st[3] = t1;
        float t2 = st[6]; st[6] = st[7]; st[7] = t2;
    }
}

__device__ __forceinline__ void cnot_odd(float (&st)[8], int lane) {
    cnot_lane(st, lane, 8, 4);   // c=1: ctrl bit6(lb3), tgt bit5(lb2)
    cnot_lane(st, lane, 2, 1);   // c=3: ctrl bit4(lb1), tgt bit3(lb0)
    {                            // c=5: ctrl bit2, tgt bit1 (intra, free)
        float t1 = st[4]; st[4] = st[6]; st[6] = t1;
        float t2 = st[5]; st[5] = st[7]; st[7] = t2;
    }
}

// ---------------------------------------------------------------------------
// Kernel 3: the full recurrence. 1 block (128 thr) per batch element,
// warp w in {0..3} simulates the VQC for gate w (i, f, g, o).
// ---------------------------------------------------------------------------
__global__ __launch_bounds__(128, 7) void k_main(
    const float* __restrict__ ipw, const float* __restrict__ ipb,
    const float* __restrict__ ing, const float* __restrict__ inb,
    const float* __restrict__ piw, const float* __restrict__ pib,
    const float* __restrict__ pfw, const float* __restrict__ pfb,
    const float* __restrict__ pgw, const float* __restrict__ pgb,
    const float* __restrict__ pow_, const float* __restrict__ pob,
    const float* __restrict__ ong, const float* __restrict__ onb,
    const float* __restrict__ outw, const float* __restrict__ outb,
    float* __restrict__ out) {
    __shared__ float s_ipw[8 * 256];    // ip_w, [j][k] row-major
    __shared__ float s_pw[4][HN * 8];   // gate projection weights, [r][q]
    __shared__ float s_wc[4][32];       // cos of weight half-angles
    __shared__ float s_ws[4][32];
    __shared__ float s_h[HN], s_c[HN];
    __shared__ float s_g[4][HN];        // gate activations i,f,g,o
    __shared__ float s_pr[8];           // tanh(proj) (pre-LN)
    __shared__ float s_ipb[8], s_ing[8], s_inb[8];

    int tid = threadIdx.x;
    int w = tid >> 5, lane = tid & 31;
    int b = blockIdx.x;

    for (int i = tid; i < 2048; i += 128) s_ipw[i] = ipw[i];
    for (int i = tid; i < 1024; i += 128) {
        s_pw[0][i] = piw[i];
        s_pw[1][i] = pfw[i];
        s_pw[2][i] = pgw[i];
        s_pw[3][i] = pow_[i];
    }
    if (tid < 128) {
        ((float*)s_wc)[tid] = g_wc[tid];
        ((float*)s_ws)[tid] = g_ws[tid];
    }
    if (tid < 8) {
        s_ipb[tid] = ipb[tid];
        s_ing[tid] = ing[tid];
        s_inb[tid] = inb[tid];
    }
    if (tid < HN) { s_h[tid] = 0.f; s_c[tid] = 0.f; }

    // per-warp gate bias in registers
    const float* pbp = (w == 0) ? pib : (w == 1) ? pfb : (w == 2) ? pgb : pob;
    float gb[4];
#pragma unroll
    for (int m = 0; m < 4; m++) gb[m] = pbp[lane + 32 * m];

    __syncthreads();

    const float* embp = g_emb + (size_t)(b * TN) * HN;
    float* outp = out + b * TN;

#pragma unroll 1
    for (int t = 0; t < TN; t++, embp += HN) {
        // ---- stage 1: cooperative raw proj (warp w computes j=2w, 2w+1) ----
        int j0 = 2 * w;
        float a0 = 0.f, a1 = 0.f;
#pragma unroll
        for (int m = 0; m < 8; m++) {
            int k = lane + 32 * m;
            float cm = (m < 4) ? embp[k] : s_h[k - 128];
            a0 = fmaf(cm, s_ipw[j0 * 256 + k], a0);
            a1 = fmaf(cm, s_ipw[j0 * 256 + 256 + k], a1);
        }
#pragma unroll
        for (int d = 16; d; d >>= 1) {
            a0 += __shfl_xor_sync(0xffffffffu, a0, d);
            a1 += __shfl_xor_sync(0xffffffffu, a1, d);
        }
        if (lane == 0) {
            s_pr[j0]     = tanhf(a0 + s_ipb[j0]);
            s_pr[j0 + 1] = tanhf(a1 + s_ipb[j0 + 1]);
        }
        __syncthreads();

        // ---- stage 2: LN over the 8 tanh(proj) values (duplicated per warp) ----
        float pj[8];
        float psum = 0.f;
#pragma unroll
        for (int j = 0; j < 8; j++) { pj[j] = s_pr[j]; psum += pj[j]; }
        float pm = psum * 0.125f;
        float pv = 0.f;
#pragma unroll
        for (int j = 0; j < 8; j++) { float d = pj[j] - pm; pv = fmaf(d, d, pv); }
        float prs = rsqrtf(pv * 0.125f + 1e-5f);

        // ---- VQC for gate w ----
        float st[8];
#pragma unroll
        for (int j = 0; j < 8; j++) st[j] = 0.0625f;  // 1/16

        // input layer: RY(q, LN(proj)[q]) for q = 0..7
        {
            float cs, sn, ang;
#define INRY(Q)                                                         \
            ang = ((pj[Q] - pm) * prs * s_ing[Q] + s_inb[Q]) * 0.5f;    \
            __sincosf(ang, &sn, &cs);                                   \
            apply_ry<Q>(st, cs, sn, lane);
            INRY(0) INRY(1) INRY(2) INRY(3) INRY(4) INRY(5) INRY(6) INRY(7)
#undef INRY
        }

        // variational layers (keep rolled for I$)
#pragma unroll 1
        for (int l = 0; l < 4; l++) {
            cnot_even(st, lane);
            cnot_odd(st, lane);
            const float* wc = &s_wc[w][l * 8];
            const float* ws = &s_ws[w][l * 8];
            apply_ry<0>(st, wc[0], ws[0], lane);
            apply_ry<1>(st, wc[1], ws[1], lane);
            apply_ry<2>(st, wc[2], ws[2], lane);
            apply_ry<3>(st, wc[3], ws[3], lane);
            apply_ry<4>(st, wc[4], ws[4], lane);
            apply_ry<5>(st, wc[5], ws[5], lane);
            apply_ry<6>(st, wc[6], ws[6], lane);
            apply_ry<7>(st, wc[7], ws[7], lane);
        }

        // ---- readout: z[q] = sum_a sign_q(a) * p_a ----
        float p0 = st[0] * st[0], p1 = st[1] * st[1];
        float p2 = st[2] * st[2], p3 = st[3] * st[3];
        float p4 = st[4] * st[4], p5 = st[5] * st[5];
        float p6 = st[6] * st[6], p7 = st[7] * st[7];
        float s01 = p0 + p1, s23 = p2 + p3, s45 = p4 + p5, s67 = p6 + p7;
        float s0123 = s01 + s23, s4567 = s45 + s67;
        float tot = s0123 + s4567;
        float z[8];
        z[0] = (lane & 16) ? -tot : tot;  // qubit 0 -> bit7 -> lane bit4
        z[1] = (lane & 8)  ? -tot : tot;
        z[2] = (lane & 4)  ? -tot : tot;
        z[3] = (lane & 2)  ? -tot : tot;
        z[4] = (lane & 1)  ? -tot : tot;
        z[5] = s0123 - s4567;                          // bit2
        z[6] = (s01 - s23) + (s45 - s67);              // bit1
        z[7] = ((p0 - p1) + (p2 - p3)) + ((p4 - p5) + (p6 - p7));  // bit0
#pragma unroll
        for (int j = 0; j < 8; j++) {
#pragma unroll
            for (int d = 16; d; d >>= 1) z[j] += __shfl_xor_sync(0xffffffffu, z[j], d);
        }

        // ---- gate projection + activation ----
#pragma unroll
        for (int m = 0; m < 4; m++) {
            int r = lane + 32 * m;
            const float4* w4 = (const float4*)&s_pw[w][r * 8];
            float4 wa = w4[0], wb = w4[1];
            float pre = gb[m];
            pre = fmaf(z[0], wa.x, pre); pre = fmaf(z[1], wa.y, pre);
            pre = fmaf(z[2], wa.z, pre); pre = fmaf(z[3], wa.w, pre);
            pre = fmaf(z[4], wb.x, pre); pre = fmaf(z[5], wb.y, pre);
            pre = fmaf(z[6], wb.z, pre); pre = fmaf(z[7], wb.w, pre);
            float val;
            if (w == 2) val = tanhf(pre);
            else        val = __fdividef(1.f, 1.f + __expf(-pre));
            s_g[w][r] = val;
        }
        __syncthreads();

        // ---- LSTM cell update + output LN + final dot (warp 0) ----
        if (w == 0) {
            float sv[4];
            float sum = 0.f, sq = 0.f;
#pragma unroll
            for (int m = 0; m < 4; m++) {
                int r = lane + 32 * m;
                float cn = fmaf(s_g[1][r], s_c[r], s_g[0][r] * s_g[2][r]);
                float hn = s_g[3][r] * tanhf(cn);
                s_c[r] = cn;
                s_h[r] = hn;
                float v = hn + embp[r];
                sv[m] = v;
                sum += v;
                sq = fmaf(v, v, sq);
            }
#pragma unroll
            for (int d = 16; d; d >>= 1) {
                sum += __shfl_xor_sync(0xffffffffu, sum, d);
                sq  += __shfl_xor_sync(0xffffffffu, sq, d);
            }
            float mean = sum * (1.f / 128.f);
            float rstd = rsqrtf(sq * (1.f / 128.f) - mean * mean + 1e-5f);
            float acc = 0.f;
#pragma unroll
            for (int m = 0; m < 4; m++) {
                int r = lane + 32 * m;
                float y = (sv[m] - mean) * rstd * ong[r] + onb[r];
                acc = fmaf(y, outw[r], acc);
            }
#pragma unroll
            for (int d = 16; d; d >>= 1) acc += __shfl_xor_sync(0xffffffffu, acc, d);
            if (lane == 0) outp[t] = acc + outb[0];
        }
        __syncthreads();
    }
}

// ---------------------------------------------------------------------------
// Launch. Input order per metadata:
// 0:x 1:pe 2:emb_w 3:emb_b 4:emb_g 5:emb_bt 6:ip_w 7:ip_b 8:in_g 9:in_b
// 10:wq_i 11:wq_f 12:wq_g 13:wq_o 14:pi_w 15:pi_b 16:pf_w 17:pf_b
// 18:pg_w 19:pg_b 20:po_w 21:po_b 22:on_g 23:on_b 24:out_w 25:out_b
// ---------------------------------------------------------------------------
extern "C" void kernel_launch(void* const* d_in, const int* in_sizes, int n_in,
                              void* d_out, int out_size) {
    const float* x     = (const float*)d_in[0];
    const float* pe    = (const float*)d_in[1];
    const float* emb_w = (const float*)d_in[2];
    const float* emb_b = (const float*)d_in[3];
    const float* emb_g = (const float*)d_in[4];
    const float* emb_bt= (const float*)d_in[5];
    const float* ip_w  = (const float*)d_in[6];
    const float* ip_b  = (const float*)d_in[7];
    const float* in_g  = (const float*)d_in[8];
    const float* in_b  = (const float*)d_in[9];
    const float* wq_i  = (const float*)d_in[10];
    const float* wq_f  = (const float*)d_in[11];
    const float* wq_g  = (const float*)d_in[12];
    const float* wq_o  = (const float*)d_in[13];
    const float* pi_w  = (const float*)d_in[14];
    const float* pi_b  = (const float*)d_in[15];
    const float* pf_w  = (const float*)d_in[16];
    const float* pf_b  = (const float*)d_in[17];
    const float* pg_w  = (const float*)d_in[18];
    const float* pg_b  = (const float*)d_in[19];
    const float* po_w  = (const float*)d_in[20];
    const float* po_b  = (const float*)d_in[21];
    const float* on_g  = (const float*)d_in[22];
    const float* on_b  = (const float*)d_in[23];
    const float* out_w = (const float*)d_in[24];
    const float* out_b = (const float*)d_in[25];
    float* out = (float*)d_out;

    k_sincos<<<1, 128>>>(wq_i, wq_f, wq_g, wq_o);
    k_emb<<<(BN * TN) / 8, 256>>>(x, pe, emb_w, emb_b, emb_g, emb_bt);
    k_main<<<BN, 128>>>(ip_w, ip_b, in_g, in_b,
                        pi_w, pi_b, pf_w, pf_b, pg_w, pg_b, po_w, po_b,
                        on_g, on_b, out_w, out_b, out);
}

// round 7
// speedup vs baseline: 1.2831x; 1.2831x over previous
#include <cuda_runtime.h>

#define BN 1024
#define TN 128
#define HN 128
#define FULL 0xffffffffu

// Scratch (static __device__, no allocation)
__device__ float g_emb[BN * TN * HN];     // 64 MB embedding
__device__ float g_proj[BN * TN * 8];     // 4 MB precomputed x-part of input projection (+bias)
__device__ float g_tv[128];               // tan(0.5*w) [gate(4)][layer(4)][qubit(8)]
__device__ float g_cv[128];               // cos(0.5*w)
__device__ float g_C2[4];                 // per-gate (prod of 32 cos)^2

// ---------------------------------------------------------------------------
// fast activations (__expf max err ~2ulp)
// ---------------------------------------------------------------------------
__device__ __forceinline__ float tanh_fast(float x) {
    float e = __expf(-2.f * fabsf(x));
    float r = __fdividef(1.f - e, 1.f + e);
    return copysignf(r, x);
}
__device__ __forceinline__ float sigmoid_fast(float x) {
    return __fdividef(1.f, 1.f + __expf(-x));
}

// ---------------------------------------------------------------------------
// Kernel 1: variational-weight trig precompute (accurate sincosf)
// ---------------------------------------------------------------------------
__global__ void k_prep(const float* __restrict__ wi, const float* __restrict__ wf,
                       const float* __restrict__ wg, const float* __restrict__ wo) {
    int i = threadIdx.x;  // 128 threads
    int gate = i >> 5, idx = i & 31;
    const float* w = (gate == 0) ? wi : (gate == 1) ? wf : (gate == 2) ? wg : wo;
    float s, c;
    sincosf(0.5f * w[idx], &s, &c);
    g_tv[i] = s / c;
    g_cv[i] = c;
    __syncthreads();
    if (i < 4) {
        float p = 1.f;
#pragma unroll 1
        for (int k = 0; k < 32; k++) p *= g_cv[i * 32 + k];
        g_C2[i] = p * p;
    }
}

// ---------------------------------------------------------------------------
// Kernel 2: emb = LN(x @ emb_w.T + emb_b) + pe[t]; also precompute
// g_proj[row][j] = sum_k emb_k * ip_w[j][k] + ip_b[j]  (x-part of input proj)
// One warp per (b,t) row.
// ---------------------------------------------------------------------------
__global__ __launch_bounds__(256) void k_emb(
    const float* __restrict__ x, const float* __restrict__ pe,
    const float* __restrict__ ew, const float* __restrict__ eb,
    const float* __restrict__ eg, const float* __restrict__ ebt,
    const float* __restrict__ ipw, const float* __restrict__ ipb) {
    int warp = threadIdx.x >> 5, lane = threadIdx.x & 31;
    int row = blockIdx.x * 8 + warp;
    if (row >= BN * TN) return;

    const float* xr = x + row * 8;
    float4 x0 = *(const float4*)xr;
    float4 x1 = *(const float4*)(xr + 4);

    float pre[4];
    float sum = 0.f, sq = 0.f;
#pragma unroll
    for (int m = 0; m < 4; m++) {
        int r = lane + 32 * m;
        const float4* wr = (const float4*)(ew + r * 8);
        float4 wa = wr[0], wb = wr[1];
        float a = eb[r];
        a = fmaf(x0.x, wa.x, a); a = fmaf(x0.y, wa.y, a);
        a = fmaf(x0.z, wa.z, a); a = fmaf(x0.w, wa.w, a);
        a = fmaf(x1.x, wb.x, a); a = fmaf(x1.y, wb.y, a);
        a = fmaf(x1.z, wb.z, a); a = fmaf(x1.w, wb.w, a);
        pre[m] = a;
        sum += a;
        sq = fmaf(a, a, sq);
    }
#pragma unroll
    for (int d = 16; d; d >>= 1) {
        sum += __shfl_xor_sync(FULL, sum, d);
        sq  += __shfl_xor_sync(FULL, sq, d);
    }
    float mean = sum * (1.f / 128.f);
    float rstd = rsqrtf(sq * (1.f / 128.f) - mean * mean + 1e-5f);
    int t = row & (TN - 1);
    float ev[4];
#pragma unroll
    for (int m = 0; m < 4; m++) {
        int r = lane + 32 * m;
        ev[m] = (pre[m] - mean) * rstd * eg[r] + ebt[r] + pe[t * HN + r];
        g_emb[row * HN + r] = ev[m];
    }
    // x-part of input projection
    float pj[8];
#pragma unroll
    for (int j = 0; j < 8; j++) {
        float a = 0.f;
#pragma unroll
        for (int m = 0; m < 4; m++) a = fmaf(ev[m], ipw[j * 256 + lane + 32 * m], a);
        pj[j] = a;
    }
#pragma unroll
    for (int j = 0; j < 8; j++) {
#pragma unroll
        for (int d = 16; d; d >>= 1) pj[j] += __shfl_xor_sync(FULL, pj[j], d);
    }
    if (lane == 0) {
#pragma unroll
        for (int j = 0; j < 8; j++) g_proj[row * 8 + j] = pj[j] + ipb[j];
    }
}

// ---------------------------------------------------------------------------
// VQC helpers. Amp index bits [7:0]; lane = bits[7:3], reg j = bits[2:0].
// Qubit q acts on bit (7-q). RY in tan form (cos factors deferred into C2).
// ---------------------------------------------------------------------------
__device__ __forceinline__ void lane_ry(float (&st)[8], float tq, int lane, int mask) {
    float sg = (lane & mask) ? tq : -tq;
#pragma unroll
    for (int j = 0; j < 8; j++) {
        float o = __shfl_xor_sync(FULL, st[j], mask);
        st[j] = fmaf(sg, o, st[j]);
    }
}
__device__ __forceinline__ void pair_ry(float (&st)[8], float tq, int a, int b) {
    float xx = st[a];
    st[a] = fmaf(-tq, st[b], xx);
    st[b] = fmaf(tq, xx, st[b]);
}

// ---------------------------------------------------------------------------
// Kernel 3: the recurrence. 1 block (128 thr) / batch element, warp w = gate w.
// ---------------------------------------------------------------------------
__global__ __launch_bounds__(128, 7) void k_main(
    const float* __restrict__ ipw,
    const float* __restrict__ ing, const float* __restrict__ inb,
    const float* __restrict__ piw, const float* __restrict__ pib,
    const float* __restrict__ pfw, const float* __restrict__ pfb,
    const float* __restrict__ pgw, const float* __restrict__ pgb,
    const float* __restrict__ pow_, const float* __restrict__ pob,
    const float* __restrict__ ong, const float* __restrict__ onb,
    const float* __restrict__ outw, const float* __restrict__ outb,
    float* __restrict__ out) {
    __shared__ float s_ipw[8 * 128];       // h-half of ip_w: [j][k]
    __shared__ float s_t[4][32];           // variational tans per gate
    __shared__ float s_pw[4][HN * 8];      // full gate projection weights [w][r*8+q]
    __shared__ float s_pr[8];              // tanh(proj) pre-LN
    __shared__ float s_g[4][HN];           // gate activations
    __shared__ float s_in2[16];            // 0.5*in_g, 0.5*in_b
    __shared__ float s_ong[HN], s_onb[HN], s_outw[HN];

    int tid = threadIdx.x;
    int w = tid >> 5, lane = tid & 31;
    int b = blockIdx.x;

    for (int i = tid; i < 1024; i += 128) {
        s_ipw[i] = ipw[(i >> 7) * 256 + 128 + (i & 127)];
        s_pw[0][i] = piw[i];
        s_pw[1][i] = pfw[i];
        s_pw[2][i] = pgw[i];
        s_pw[3][i] = pow_[i];
    }
    ((float*)s_t)[tid] = g_tv[tid];
    if (tid < 8) { s_in2[tid] = 0.5f * ing[tid]; s_in2[8 + tid] = 0.5f * inb[tid]; }
    s_ong[tid] = ong[tid]; s_onb[tid] = onb[tid]; s_outw[tid] = outw[tid];

    const float* pb = (w == 0) ? pib : (w == 1) ? pfb : (w == 2) ? pgb : pob;
    float gb[4];
#pragma unroll
    for (int m = 0; m < 4; m++) gb[m] = pb[lane + 32 * m];
    float C2 = g_C2[w];
    float ob0 = outb[0];

    // Composed CNOT-block permutation: src_lane + publish selector (constant)
    int l0 = lane & 1, l1 = (lane >> 1) & 1, l2 = (lane >> 2) & 1,
        l3 = (lane >> 3) & 1, l4 = (lane >> 4) & 1;
    int srcL = (l4 << 4) | ((l3 ^ l4) << 3) | ((l2 ^ l3) << 2) |
               ((l1 ^ l2 ^ l3) << 1) | (l0 ^ l1);
    bool pp = (l0 != 0);

    float h[4] = {0.f, 0.f, 0.f, 0.f}, c[4] = {0.f, 0.f, 0.f, 0.f};
    __syncthreads();

    long rowbase = (long)b * TN;

#pragma unroll 1
    for (int t = 0; t < TN; t++) {
        // ---- stage 1: h-part of proj (x-part precomputed in g_proj) ----
        int j0 = 2 * w;
        float a0 = 0.f, a1 = 0.f;
#pragma unroll
        for (int m = 0; m < 4; m++) {
            int k = lane + 32 * m;
            a0 = fmaf(h[m], s_ipw[j0 * 128 + k], a0);
            a1 = fmaf(h[m], s_ipw[j0 * 128 + 128 + k], a1);
        }
#pragma unroll
        for (int d = 16; d; d >>= 1) {
            a0 += __shfl_xor_sync(FULL, a0, d);
            a1 += __shfl_xor_sync(FULL, a1, d);
        }
        if (lane == 0) {
            const float* gp = g_proj + (rowbase + t) * 8;
            s_pr[j0]     = tanh_fast(a0 + gp[j0]);
            s_pr[j0 + 1] = tanh_fast(a1 + gp[j0 + 1]);
        }
        __syncthreads();

        // ---- stage 2: LN over the 8 proj values (warp-uniform) ----
        float pj[8], psum = 0.f;
#pragma unroll
        for (int j = 0; j < 8; j++) { pj[j] = s_pr[j]; psum += pj[j]; }
        float pm = psum * 0.125f;
        float pv = 0.f;
#pragma unroll
        for (int j = 0; j < 8; j++) { float d = pj[j] - pm; pv = fmaf(d, d, pv); }
        float prs = rsqrtf(pv * 0.125f + 1e-5f);

        // ---- input layer as a product state (zero shuffles) ----
        float st[8];
        float P = 0.0625f;
        float fm5, fp5, fm6, fp6, fm7, fp7;
        {
            float sn, cs, ang;
#define ANG(Q) ang = fmaf((pj[Q] - pm) * prs, s_in2[Q], s_in2[8 + Q]); \
               __sincosf(ang, &sn, &cs);
            ANG(0) P *= (lane & 16) ? (cs + sn) : (cs - sn);
            ANG(1) P *= (lane & 8)  ? (cs + sn) : (cs - sn);
            ANG(2) P *= (lane & 4)  ? (cs + sn) : (cs - sn);
            ANG(3) P *= (lane & 2)  ? (cs + sn) : (cs - sn);
            ANG(4) P *= (lane & 1)  ? (cs + sn) : (cs - sn);
            ANG(5) fm5 = cs - sn; fp5 = cs + sn;
            ANG(6) fm6 = cs - sn; fp6 = cs + sn;
            ANG(7) fm7 = cs - sn; fp7 = cs + sn;
#undef ANG
        }
        {
            float r0 = P * (fm5 * fm6), r1 = P * (fm5 * fp6);
            float r2 = P * (fp5 * fm6), r3 = P * (fp5 * fp6);
            st[0] = r0 * fm7; st[1] = r0 * fp7;
            st[2] = r1 * fm7; st[3] = r1 * fp7;
            st[4] = r2 * fm7; st[5] = r2 * fp7;
            st[6] = r3 * fm7; st[7] = r3 * fp7;
        }

        // ---- variational layers ----
#pragma unroll 1
        for (int l = 0; l < 4; l++) {
            // all 7 CNOTs composed: one indexed shuffle per register
            float n0 = __shfl_sync(FULL, pp ? st[4] : st[0], srcL);
            float n1 = __shfl_sync(FULL, pp ? st[5] : st[1], srcL);
            float n2 = __shfl_sync(FULL, pp ? st[7] : st[3], srcL);
            float n3 = __shfl_sync(FULL, pp ? st[6] : st[2], srcL);
            float n4 = __shfl_sync(FULL, pp ? st[3] : st[7], srcL);
            float n5 = __shfl_sync(FULL, pp ? st[2] : st[6], srcL);
            float n6 = __shfl_sync(FULL, pp ? st[0] : st[4], srcL);
            float n7 = __shfl_sync(FULL, pp ? st[1] : st[5], srcL);
            st[0] = n0; st[1] = n1; st[2] = n2; st[3] = n3;
            st[4] = n4; st[5] = n5; st[6] = n6; st[7] = n7;

            const float* tv = &s_t[w][l * 8];
            lane_ry(st, tv[0], lane, 16);
            lane_ry(st, tv[1], lane, 8);
            lane_ry(st, tv[2], lane, 4);
            lane_ry(st, tv[3], lane, 2);
            lane_ry(st, tv[4], lane, 1);
            { float tq = tv[5];
              pair_ry(st, tq, 0, 4); pair_ry(st, tq, 1, 5);
              pair_ry(st, tq, 2, 6); pair_ry(st, tq, 3, 7); }
            { float tq = tv[6];
              pair_ry(st, tq, 0, 2); pair_ry(st, tq, 1, 3);
              pair_ry(st, tq, 4, 6); pair_ry(st, tq, 5, 7); }
            { float tq = tv[7];
              pair_ry(st, tq, 0, 1); pair_ry(st, tq, 2, 3);
              pair_ry(st, tq, 4, 5); pair_ry(st, tq, 6, 7); }
        }

        // ---- readout: local Walsh coefficients over registers ----
        float q0 = st[0] * st[0], q1 = st[1] * st[1];
        float q2 = st[2] * st[2], q3 = st[3] * st[3];
        float q4 = st[4] * st[4], q5 = st[5] * st[5];
        float q6 = st[6] * st[6], q7 = st[7] * st[7];
        float e01 = q0 + q1, e23 = q2 + q3, e45 = q4 + q5, e67 = q6 + q7;
        float A = e01 + e23, B = e45 + e67;
        float tot = A + B;
        float z5 = A - B;                                             // qubit5 (reg bit2)
        float z6 = (e01 - e23) + (e45 - e67);                         // qubit6 (reg bit1)
        float z7 = ((q0 - q1) + (q2 - q3)) + ((q4 - q5) + (q6 - q7)); // qubit7 (reg bit0)

        // Walsh-Hadamard butterfly over lanes: lane (1<<(4-q)) ends with z_q
        float wz = tot;
#pragma unroll
        for (int d = 16; d; d >>= 1) {
            float o = __shfl_xor_sync(FULL, wz, d);
            wz = (lane & d) ? (o - wz) : (wz + o);
        }
        // plain reductions for z5, z6, z7
#pragma unroll
        for (int d = 16; d; d >>= 1) {
            z5 += __shfl_xor_sync(FULL, z5, d);
            z6 += __shfl_xor_sync(FULL, z6, d);
            z7 += __shfl_xor_sync(FULL, z7, d);
        }
        float z[8];
        z[0] = C2 * __shfl_sync(FULL, wz, 16);
        z[1] = C2 * __shfl_sync(FULL, wz, 8);
        z[2] = C2 * __shfl_sync(FULL, wz, 4);
        z[3] = C2 * __shfl_sync(FULL, wz, 2);
        z[4] = C2 * __shfl_sync(FULL, wz, 1);
        z[5] = C2 * z5;
        z[6] = C2 * z6;
        z[7] = C2 * z7;

        // ---- gate projection + activation (full per-row weights) ----
#pragma unroll
        for (int m = 0; m < 4; m++) {
            int r = lane + 32 * m;
            const float4* w4 = (const float4*)&s_pw[w][r * 8];
            float4 wa = w4[0], wb = w4[1];
            float pre = gb[m];
            pre = fmaf(z[0], wa.x, pre); pre = fmaf(z[1], wa.y, pre);
            pre = fmaf(z[2], wa.z, pre); pre = fmaf(z[3], wa.w, pre);
            pre = fmaf(z[4], wb.x, pre); pre = fmaf(z[5], wb.y, pre);
            pre = fmaf(z[6], wb.z, pre); pre = fmaf(z[7], wb.w, pre);
            float act = (w == 2) ? tanh_fast(pre) : sigmoid_fast(pre);
            s_g[w][r] = act;
        }
        __syncthreads();

        // ---- epilogue: all warps update h,c redundantly (regs) ----
#pragma unroll
        for (int m = 0; m < 4; m++) {
            int r = lane + 32 * m;
            float it = s_g[0][r], ft = s_g[1][r], gt = s_g[2][r], ot = s_g[3][r];
            c[m] = fmaf(ft, c[m], it * gt);
            h[m] = ot * tanh_fast(c[m]);
        }
        // output LN + dot: rotate across warps to balance SMSPs
        if (w == (t & 3)) {
            const float* embp = g_emb + (rowbase + t) * HN;
            float v[4], sum = 0.f, sq = 0.f;
#pragma unroll
            for (int m = 0; m < 4; m++) {
                v[m] = h[m] + embp[lane + 32 * m];
                sum += v[m];
                sq = fmaf(v[m], v[m], sq);
            }
#pragma unroll
            for (int d = 16; d; d >>= 1) {
                sum += __shfl_xor_sync(FULL, sum, d);
                sq  += __shfl_xor_sync(FULL, sq, d);
            }
            float mean = sum * (1.f / 128.f);
            float rstd = rsqrtf(sq * (1.f / 128.f) - mean * mean + 1e-5f);
            float acc = 0.f;
#pragma unroll
            for (int m = 0; m < 4; m++) {
                int r = lane + 32 * m;
                float y = (v[m] - mean) * rstd * s_ong[r] + s_onb[r];
                acc = fmaf(y, s_outw[r], acc);
            }
#pragma unroll
            for (int d = 16; d; d >>= 1) acc += __shfl_xor_sync(FULL, acc, d);
            if (lane == 0) out[rowbase + t] = acc + ob0;
        }
    }
}

// ---------------------------------------------------------------------------
// Launch. Input order:
// 0:x 1:pe 2:emb_w 3:emb_b 4:emb_g 5:emb_bt 6:ip_w 7:ip_b 8:in_g 9:in_b
// 10:wq_i 11:wq_f 12:wq_g 13:wq_o 14:pi_w 15:pi_b 16:pf_w 17:pf_b
// 18:pg_w 19:pg_b 20:po_w 21:po_b 22:on_g 23:on_b 24:out_w 25:out_b
// ---------------------------------------------------------------------------
extern "C" void kernel_launch(void* const* d_in, const int* in_sizes, int n_in,
                              void* d_out, int out_size) {
    const float* x     = (const float*)d_in[0];
    const float* pe    = (const float*)d_in[1];
    const float* emb_w = (const float*)d_in[2];
    const float* emb_b = (const float*)d_in[3];
    const float* emb_g = (const float*)d_in[4];
    const float* emb_bt= (const float*)d_in[5];
    const float* ip_w  = (const float*)d_in[6];
    const float* ip_b  = (const float*)d_in[7];
    const float* in_g  = (const float*)d_in[8];
    const float* in_b  = (const float*)d_in[9];
    const float* wq_i  = (const float*)d_in[10];
    const float* wq_f  = (const float*)d_in[11];
    const float* wq_g  = (const float*)d_in[12];
    const float* wq_o  = (const float*)d_in[13];
    const float* pi_w  = (const float*)d_in[14];
    const float* pi_b  = (const float*)d_in[15];
    const float* pf_w  = (const float*)d_in[16];
    const float* pf_b  = (const float*)d_in[17];
    const float* pg_w  = (const float*)d_in[18];
    const float* pg_b  = (const float*)d_in[19];
    const float* po_w  = (const float*)d_in[20];
    const float* po_b  = (const float*)d_in[21];
    const float* on_g  = (const float*)d_in[22];
    const float* on_b  = (const float*)d_in[23];
    const float* out_w = (const float*)d_in[24];
    const float* out_b = (const float*)d_in[25];
    float* out = (float*)d_out;

    k_prep<<<1, 128>>>(wq_i, wq_f, wq_g, wq_o);
    k_emb<<<(BN * TN) / 8, 256>>>(x, pe, emb_w, emb_b, emb_g, emb_bt, ip_w, ip_b);
    k_main<<<BN, 128>>>(ip_w, in_g, in_b,
                        pi_w, pi_b, pf_w, pf_b, pg_w, pg_b, po_w, po_b,
                        on_g, on_b, out_w, out_b, out);
}

// round 9
// speedup vs baseline: 1.3260x; 1.0335x over previous
#include <cuda_runtime.h>

#define BN 1024
#define TN 128
#define HN 128
#define FULL 0xffffffffu

// Scratch (static __device__, no allocation)
__device__ float g_emb[BN * TN * HN];     // 64 MB embedding
__device__ float g_proj[BN * TN * 8];     // 4 MB precomputed x-part of input projection (+bias)

// ---------------------------------------------------------------------------
// fast activations (__expf max err ~2ulp)
// ---------------------------------------------------------------------------
__device__ __forceinline__ float tanh_fast(float x) {
    float e = __expf(-2.f * fabsf(x));
    float r = __fdividef(1.f - e, 1.f + e);
    return copysignf(r, x);
}
__device__ __forceinline__ float sigmoid_fast(float x) {
    return __fdividef(1.f, 1.f + __expf(-x));
}

// ---------------------------------------------------------------------------
// Kernel 1: emb = LN(x @ emb_w.T + emb_b) + pe[t]; also precompute
// g_proj[row][j] = sum_k emb_k * ip_w[j][k] + ip_b[j]  (x-part of input proj)
// One warp per (b,t) row.
// ---------------------------------------------------------------------------
__global__ __launch_bounds__(256) void k_emb(
    const float* __restrict__ x, const float* __restrict__ pe,
    const float* __restrict__ ew, const float* __restrict__ eb,
    const float* __restrict__ eg, const float* __restrict__ ebt,
    const float* __restrict__ ipw, const float* __restrict__ ipb) {
    int warp = threadIdx.x >> 5, lane = threadIdx.x & 31;
    int row = blockIdx.x * 8 + warp;
    if (row >= BN * TN) return;

    const float* xr = x + row * 8;
    float4 x0 = *(const float4*)xr;
    float4 x1 = *(const float4*)(xr + 4);

    float pre[4];
    float sum = 0.f, sq = 0.f;
#pragma unroll
    for (int m = 0; m < 4; m++) {
        int r = lane + 32 * m;
        const float4* wr = (const float4*)(ew + r * 8);
        float4 wa = wr[0], wb = wr[1];
        float a = eb[r];
        a = fmaf(x0.x, wa.x, a); a = fmaf(x0.y, wa.y, a);
        a = fmaf(x0.z, wa.z, a); a = fmaf(x0.w, wa.w, a);
        a = fmaf(x1.x, wb.x, a); a = fmaf(x1.y, wb.y, a);
        a = fmaf(x1.z, wb.z, a); a = fmaf(x1.w, wb.w, a);
        pre[m] = a;
        sum += a;
        sq = fmaf(a, a, sq);
    }
#pragma unroll
    for (int d = 16; d; d >>= 1) {
        sum += __shfl_xor_sync(FULL, sum, d);
        sq  += __shfl_xor_sync(FULL, sq, d);
    }
    float mean = sum * (1.f / 128.f);
    float rstd = rsqrtf(sq * (1.f / 128.f) - mean * mean + 1e-5f);
    int t = row & (TN - 1);
    float ev[4];
#pragma unroll
    for (int m = 0; m < 4; m++) {
        int r = lane + 32 * m;
        ev[m] = (pre[m] - mean) * rstd * eg[r] + ebt[r] + pe[t * HN + r];
        g_emb[row * HN + r] = ev[m];
    }
    // x-part of input projection
    float pj[8];
#pragma unroll
    for (int j = 0; j < 8; j++) {
        float a = 0.f;
#pragma unroll
        for (int m = 0; m < 4; m++) a = fmaf(ev[m], ipw[j * 256 + lane + 32 * m], a);
        pj[j] = a;
    }
#pragma unroll
    for (int j = 0; j < 8; j++) {
#pragma unroll
        for (int d = 16; d; d >>= 1) pj[j] += __shfl_xor_sync(FULL, pj[j], d);
    }
    if (lane == 0) {
#pragma unroll
        for (int j = 0; j < 8; j++) g_proj[row * 8 + j] = pj[j] + ipb[j];
    }
}

// ---------------------------------------------------------------------------
// VQC helpers. Amp index bits [7:0]; lane = bits[7:3], reg j = bits[2:0].
// Qubit q acts on bit (7-q). RY in tan form (cos factors deferred into C2).
// ---------------------------------------------------------------------------
__device__ __forceinline__ void lane_ry(float (&st)[8], float tq, int lane, int mask) {
    float sg = (lane & mask) ? tq : -tq;
#pragma unroll
    for (int j = 0; j < 8; j++) {
        float o = __shfl_xor_sync(FULL, st[j], mask);
        st[j] = fmaf(sg, o, st[j]);
    }
}
__device__ __forceinline__ void pair_ry(float (&st)[8], float tq, int a, int b) {
    float xx = st[a];
    st[a] = fmaf(-tq, st[b], xx);
    st[b] = fmaf(tq, xx, st[b]);
}

// ---------------------------------------------------------------------------
// Kernel 2: the recurrence. 1 block (128 thr) / batch element, warp w = gate w.
// ---------------------------------------------------------------------------
__global__ __launch_bounds__(128, 7) void k_main(
    const float* __restrict__ ipw,
    const float* __restrict__ ing, const float* __restrict__ inb,
    const float* __restrict__ wqi, const float* __restrict__ wqf,
    const float* __restrict__ wqg, const float* __restrict__ wqo,
    const float* __restrict__ piw, const float* __restrict__ pib,
    const float* __restrict__ pfw, const float* __restrict__ pfb,
    const float* __restrict__ pgw, const float* __restrict__ pgb,
    const float* __restrict__ pow_, const float* __restrict__ pob,
    const float* __restrict__ ong, const float* __restrict__ onb,
    const float* __restrict__ outw, const float* __restrict__ outb,
    float* __restrict__ out) {
    __shared__ float s_ipw[8 * 128];       // h-half of ip_w: [j][k]
    __shared__ float s_t[4][32];           // variational tans per gate
    __shared__ float s_pw[4][HN * 8];      // full gate projection weights [w][r*8+q]
    __shared__ float s_pr[8];              // tanh(proj) pre-LN
    __shared__ float s_g[4][HN];           // gate activations
    __shared__ float s_in2[16];            // 0.5*in_g, 0.5*in_b
    __shared__ float s_ong[HN], s_onb[HN], s_outw[HN];

    int tid = threadIdx.x;
    int w = tid >> 5, lane = tid & 31;
    int b = blockIdx.x;

    for (int i = tid; i < 1024; i += 128) {
        s_ipw[i] = ipw[(i >> 7) * 256 + 128 + (i & 127)];
        s_pw[0][i] = piw[i];
        s_pw[1][i] = pfw[i];
        s_pw[2][i] = pgw[i];
        s_pw[3][i] = pow_[i];
    }
    // per-warp variational trig: tans into shared, C2 via product-reduce
    const float* wq = (w == 0) ? wqi : (w == 1) ? wqf : (w == 2) ? wqg : wqo;
    float C2;
    {
        float s, cc;
        sincosf(0.5f * wq[lane], &s, &cc);
        s_t[w][lane] = s / cc;
        float p = cc;
#pragma unroll
        for (int d = 16; d; d >>= 1) p *= __shfl_xor_sync(FULL, p, d);
        C2 = p * p;
    }
    if (tid < 8) { s_in2[tid] = 0.5f * ing[tid]; s_in2[8 + tid] = 0.5f * inb[tid]; }
    s_ong[tid] = ong[tid]; s_onb[tid] = onb[tid]; s_outw[tid] = outw[tid];

    const float* pb = (w == 0) ? pib : (w == 1) ? pfb : (w == 2) ? pgb : pob;
    float gb[4];
#pragma unroll
    for (int m = 0; m < 4; m++) gb[m] = pb[lane + 32 * m];
    float ob0 = outb[0];

    // Composed CNOT-block permutation: src_lane + publish selector (constant)
    int l0 = lane & 1, l1 = (lane >> 1) & 1, l2 = (lane >> 2) & 1,
        l3 = (lane >> 3) & 1, l4 = (lane >> 4) & 1;
    int srcL = (l4 << 4) | ((l3 ^ l4) << 3) | ((l2 ^ l3) << 2) |
               ((l1 ^ l2 ^ l3) << 1) | (l0 ^ l1);
    bool pp = (l0 != 0);

    float h[4] = {0.f, 0.f, 0.f, 0.f}, c[4] = {0.f, 0.f, 0.f, 0.f};
    __syncthreads();

    long rowbase = (long)b * TN;
    int j0 = 2 * w;

    // pipelined prefetch of the x-projection pair (consumed at stage-1 end)
    float gpv = 0.f;
    if (lane < 2) gpv = g_proj[rowbase * 8 + j0 + lane];

#pragma unroll 1
    for (int t = 0; t < TN; t++) {
        // ---- early prefetch of emb row for this iteration's epilogue warp ----
        float pv[4];
        bool epi = (w == (t & 3));
        if (epi) {
            const float* embp = g_emb + (rowbase + t) * HN;
#pragma unroll
            for (int m = 0; m < 4; m++) pv[m] = embp[lane + 32 * m];
        }

        // ---- stage 1: h-part of proj; 2-value packed reduction ----
        float a0 = 0.f, a1 = 0.f;
#pragma unroll
        for (int m = 0; m < 4; m++) {
            int k = lane + 32 * m;
            a0 = fmaf(h[m], s_ipw[j0 * 128 + k], a0);
            a1 = fmaf(h[m], s_ipw[j0 * 128 + 128 + k], a1);
        }
        {
            float v = (lane & 1) ? a0 : a1;
            float o = __shfl_xor_sync(FULL, v, 1);
            if (lane & 1) a1 += o; else a0 += o;
            float r = (lane & 1) ? a1 : a0;
#pragma unroll
            for (int d = 2; d <= 16; d <<= 1) r += __shfl_xor_sync(FULL, r, d);
            if (lane < 2) s_pr[j0 + lane] = tanh_fast(r + gpv);
        }
        __syncthreads();
        // reissue prefetch for next iteration (latency hidden by the VQC)
        if (lane < 2) {
            int tn = (t + 1 < TN) ? (t + 1) : t;
            gpv = g_proj[(rowbase + tn) * 8 + j0 + lane];
        }

        // ---- stage 2: LN over the 8 proj values (warp-uniform) ----
        float pj[8], psum = 0.f;
#pragma unroll
        for (int j = 0; j < 8; j++) { pj[j] = s_pr[j]; psum += pj[j]; }
        float pm = psum * 0.125f;
        float pvv = 0.f;
#pragma unroll
        for (int j = 0; j < 8; j++) { float d = pj[j] - pm; pvv = fmaf(d, d, pvv); }
        float prs = rsqrtf(pvv * 0.125f + 1e-5f);

        // ---- input layer as a product state (zero shuffles) ----
        float st[8];
        float P = 0.0625f;
        float fm5, fp5, fm6, fp6, fm7, fp7;
        {
            float sn, cs, ang;
#define ANG(Q) ang = fmaf((pj[Q] - pm) * prs, s_in2[Q], s_in2[8 + Q]); \
               __sincosf(ang, &sn, &cs);
            ANG(0) P *= (lane & 16) ? (cs + sn) : (cs - sn);
            ANG(1) P *= (lane & 8)  ? (cs + sn) : (cs - sn);
            ANG(2) P *= (lane & 4)  ? (cs + sn) : (cs - sn);
            ANG(3) P *= (lane & 2)  ? (cs + sn) : (cs - sn);
            ANG(4) P *= (lane & 1)  ? (cs + sn) : (cs - sn);
            ANG(5) fm5 = cs - sn; fp5 = cs + sn;
            ANG(6) fm6 = cs - sn; fp6 = cs + sn;
            ANG(7) fm7 = cs - sn; fp7 = cs + sn;
#undef ANG
        }
        {
            float r0 = P * (fm5 * fm6), r1 = P * (fm5 * fp6);
            float r2 = P * (fp5 * fm6), r3 = P * (fp5 * fp6);
            st[0] = r0 * fm7; st[1] = r0 * fp7;
            st[2] = r1 * fm7; st[3] = r1 * fp7;
            st[4] = r2 * fm7; st[5] = r2 * fp7;
            st[6] = r3 * fm7; st[7] = r3 * fp7;
        }

        // ---- variational layers ----
#pragma unroll 1
        for (int l = 0; l < 4; l++) {
            // all 7 CNOTs composed: one indexed shuffle per register
            float n0 = __shfl_sync(FULL, pp ? st[4] : st[0], srcL);
            float n1 = __shfl_sync(FULL, pp ? st[5] : st[1], srcL);
            float n2 = __shfl_sync(FULL, pp ? st[7] : st[3], srcL);
            float n3 = __shfl_sync(FULL, pp ? st[6] : st[2], srcL);
            float n4 = __shfl_sync(FULL, pp ? st[3] : st[7], srcL);
            float n5 = __shfl_sync(FULL, pp ? st[2] : st[6], srcL);
            float n6 = __shfl_sync(FULL, pp ? st[0] : st[4], srcL);
            float n7 = __shfl_sync(FULL, pp ? st[1] : st[5], srcL);
            st[0] = n0; st[1] = n1; st[2] = n2; st[3] = n3;
            st[4] = n4; st[5] = n5; st[6] = n6; st[7] = n7;

            // vectorized tan loads (2 x LDS.128 instead of 8 scalar LDS)
            float4 ta = *(const float4*)&s_t[w][l * 8];
            float4 tb = *(const float4*)&s_t[w][l * 8 + 4];
            lane_ry(st, ta.x, lane, 16);
            lane_ry(st, ta.y, lane, 8);
            lane_ry(st, ta.z, lane, 4);
            lane_ry(st, ta.w, lane, 2);
            lane_ry(st, tb.x, lane, 1);
            { float tq = tb.y;
              pair_ry(st, tq, 0, 4); pair_ry(st, tq, 1, 5);
              pair_ry(st, tq, 2, 6); pair_ry(st, tq, 3, 7); }
            { float tq = tb.z;
              pair_ry(st, tq, 0, 2); pair_ry(st, tq, 1, 3);
              pair_ry(st, tq, 4, 6); pair_ry(st, tq, 5, 7); }
            { float tq = tb.w;
              pair_ry(st, tq, 0, 1); pair_ry(st, tq, 2, 3);
              pair_ry(st, tq, 4, 5); pair_ry(st, tq, 6, 7); }
        }

        // ---- readout: local Walsh coefficients over registers ----
        float q0 = st[0] * st[0], q1 = st[1] * st[1];
        float q2 = st[2] * st[2], q3 = st[3] * st[3];
        float q4 = st[4] * st[4], q5 = st[5] * st[5];
        float q6 = st[6] * st[6], q7 = st[7] * st[7];
        float e01 = q0 + q1, e23 = q2 + q3, e45 = q4 + q5, e67 = q6 + q7;
        float A = e01 + e23, B = e45 + e67;
        float tot = A + B;
        float z5 = A - B;                                             // qubit5 (reg bit2)
        float z6 = (e01 - e23) + (e45 - e67);                         // qubit6 (reg bit1)
        float z7 = ((q0 - q1) + (q2 - q3)) + ((q4 - q5) + (q6 - q7)); // qubit7 (reg bit0)

        // Walsh-Hadamard butterfly over lanes: lane (1<<(4-q)) ends with z_q
        float wz = tot;
#pragma unroll
        for (int d = 16; d; d >>= 1) {
            float o = __shfl_xor_sync(FULL, wz, d);
            wz = (lane & d) ? (o - wz) : (wz + o);
        }
        // packed 3-value reduction for z5, z6, z7 (9 SHFL instead of 15)
        float Z5, Z6, Z7;
        {
            float v1 = (lane & 1) ? z5 : z7;
            float o1 = __shfl_xor_sync(FULL, v1, 1);
            float o2 = __shfl_xor_sync(FULL, z6, 1);
            if (lane & 1) { z7 += o1; } else { z5 += o1; z6 += o2; }
            float v2 = (lane & 1) ? z7 : ((lane & 2) ? z5 : z6);
            float o3 = __shfl_xor_sync(FULL, v2, 2);
            int m4 = lane & 3;
            float live;
            if (m4 == 0)      { z5 += o3; live = z5; }
            else if (m4 == 1) { z7 += o3; live = z7; }
            else if (m4 == 2) { z6 += o3; live = z6; }
            else live = 0.f;
#pragma unroll
            for (int d = 4; d <= 16; d <<= 1) live += __shfl_xor_sync(FULL, live, d);
            Z5 = __shfl_sync(FULL, live, 0);
            Z7 = __shfl_sync(FULL, live, 1);
            Z6 = __shfl_sync(FULL, live, 2);
        }
        float z[8];
        z[0] = C2 * __shfl_sync(FULL, wz, 16);
        z[1] = C2 * __shfl_sync(FULL, wz, 8);
        z[2] = C2 * __shfl_sync(FULL, wz, 4);
        z[3] = C2 * __shfl_sync(FULL, wz, 2);
        z[4] = C2 * __shfl_sync(FULL, wz, 1);
        z[5] = C2 * Z5;
        z[6] = C2 * Z6;
        z[7] = C2 * Z7;

        // ---- gate projection + activation (full per-row weights) ----
#pragma unroll
        for (int m = 0; m < 4; m++) {
            int r = lane + 32 * m;
            const float4* w4 = (const float4*)&s_pw[w][r * 8];
            float4 wa = w4[0], wb = w4[1];
            float pre = gb[m];
            pre = fmaf(z[0], wa.x, pre); pre = fmaf(z[1], wa.y, pre);
            pre = fmaf(z[2], wa.z, pre); pre = fmaf(z[3], wa.w, pre);
            pre = fmaf(z[4], wb.x, pre); pre = fmaf(z[5], wb.y, pre);
            pre = fmaf(z[6], wb.z, pre); pre = fmaf(z[7], wb.w, pre);
            float act = (w == 2) ? tanh_fast(pre) : sigmoid_fast(pre);
            s_g[w][r] = act;
        }
        __syncthreads();

        // ---- epilogue: all warps update h,c redundantly (regs) ----
#pragma unroll
        for (int m = 0; m < 4; m++) {
            int r = lane + 32 * m;
            float it = s_g[0][r], ft = s_g[1][r], gt = s_g[2][r], ot = s_g[3][r];
            c[m] = fmaf(ft, c[m], it * gt);
            h[m] = ot * tanh_fast(c[m]);
        }
        // output LN + dot: rotate across warps to balance SMSPs
        if (epi) {
            float v[4], sum = 0.f, sq = 0.f;
#pragma unroll
            for (int m = 0; m < 4; m++) {
                v[m] = h[m] + pv[m];
                sum += v[m];
                sq = fmaf(v[m], v[m], sq);
            }
            // packed 2-value reduction (7 SHFL instead of 10)
            {
                float vv = (lane & 1) ? sum : sq;
                float o = __shfl_xor_sync(FULL, vv, 1);
                if (lane & 1) sq += o; else sum += o;
                float r = (lane & 1) ? sq : sum;
#pragma unroll
                for (int d = 2; d <= 16; d <<= 1) r += __shfl_xor_sync(FULL, r, d);
                sum = __shfl_sync(FULL, r, 0);
                sq  = __shfl_sync(FULL, r, 1);
            }
            float mean = sum * (1.f / 128.f);
            float rstd = rsqrtf(sq * (1.f / 128.f) - mean * mean + 1e-5f);
            float acc = 0.f;
#pragma unroll
            for (int m = 0; m < 4; m++) {
                int r = lane + 32 * m;
                float y = (v[m] - mean) * rstd * s_ong[r] + s_onb[r];
                acc = fmaf(y, s_outw[r], acc);
            }
#pragma unroll
            for (int d = 16; d; d >>= 1) acc += __shfl_xor_sync(FULL, acc, d);
            if (lane == 0) out[rowbase + t] = acc + ob0;
        }
    }
}

// ---------------------------------------------------------------------------
// Launch. Input order:
// 0:x 1:pe 2:emb_w 3:emb_b 4:emb_g 5:emb_bt 6:ip_w 7:ip_b 8:in_g 9:in_b
// 10:wq_i 11:wq_f 12:wq_g 13:wq_o 14:pi_w 15:pi_b 16:pf_w 17:pf_b
// 18:pg_w 19:pg_b 20:po_w 21:po_b 22:on_g 23:on_b 24:out_w 25:out_b
// ---------------------------------------------------------------------------
extern "C" void kernel_launch(void* const* d_in, const int* in_sizes, int n_in,
                              void* d_out, int out_size) {
    const float* x     = (const float*)d_in[0];
    const float* pe    = (const float*)d_in[1];
    const float* emb_w = (const float*)d_in[2];
    const float* emb_b = (const float*)d_in[3];
    const float* emb_g = (const float*)d_in[4];
    const float* emb_bt= (const float*)d_in[5];
    const float* ip_w  = (const float*)d_in[6];
    const float* ip_b  = (const float*)d_in[7];
    const float* in_g  = (const float*)d_in[8];
    const float* in_b  = (const float*)d_in[9];
    const float* wq_i  = (const float*)d_in[10];
    const float* wq_f  = (const float*)d_in[11];
    const float* wq_g  = (const float*)d_in[12];
    const float* wq_o  = (const float*)d_in[13];
    const float* pi_w  = (const float*)d_in[14];
    const float* pi_b  = (const float*)d_in[15];
    const float* pf_w  = (const float*)d_in[16];
    const float* pf_b  = (const float*)d_in[17];
    const float* pg_w  = (const float*)d_in[18];
    const float* pg_b  = (const float*)d_in[19];
    const float* po_w  = (const float*)d_in[20];
    const float* po_b  = (const float*)d_in[21];
    const float* on_g  = (const float*)d_in[22];
    const float* on_b  = (const float*)d_in[23];
    const float* out_w = (const float*)d_in[24];
    const float* out_b = (const float*)d_in[25];
    float* out = (float*)d_out;

    k_emb<<<(BN * TN) / 8, 256>>>(x, pe, emb_w, emb_b, emb_g, emb_bt, ip_w, ip_b);
    k_main<<<BN, 128>>>(ip_w, in_g, in_b,
                        wq_i, wq_f, wq_g, wq_o,
                        pi_w, pi_b, pf_w, pf_b, pg_w, pg_b, po_w, po_b,
                        on_g, on_b, out_w, out_b, out);
}

// round 10
// speedup vs baseline: 1.4221x; 1.0725x over previous
#include <cuda_runtime.h>

#define BN 1024
#define TN 128
#define HN 128
#define FULL 0xffffffffu

// Scratch (static __device__, no allocation)
__device__ float g_emb[BN * TN * HN];     // 64 MB embedding
__device__ float g_proj[BN * TN * 8];     // 4 MB precomputed x-part of input projection (+bias)

// ---------------------------------------------------------------------------
// fast activations (__expf max err ~2ulp)
// ---------------------------------------------------------------------------
__device__ __forceinline__ float tanh_fast(float x) {
    float e = __expf(-2.f * fabsf(x));
    float r = __fdividef(1.f - e, 1.f + e);
    return copysignf(r, x);
}
__device__ __forceinline__ float sigmoid_fast(float x) {
    return __fdividef(1.f, 1.f + __expf(-x));
}

// ---------------------------------------------------------------------------
// Kernel 1: emb = LN(x @ emb_w.T + emb_b) + pe[t]; also precompute
// g_proj[row][j] = sum_k emb_k * ip_w[j][k] + ip_b[j]  (x-part of input proj)
// One warp per (b,t) row.
// ---------------------------------------------------------------------------
__global__ __launch_bounds__(256) void k_emb(
    const float* __restrict__ x, const float* __restrict__ pe,
    const float* __restrict__ ew, const float* __restrict__ eb,
    const float* __restrict__ eg, const float* __restrict__ ebt,
    const float* __restrict__ ipw, const float* __restrict__ ipb) {
    int warp = threadIdx.x >> 5, lane = threadIdx.x & 31;
    int row = blockIdx.x * 8 + warp;
    if (row >= BN * TN) return;

    const float* xr = x + row * 8;
    float4 x0 = *(const float4*)xr;
    float4 x1 = *(const float4*)(xr + 4);

    float pre[4];
    float sum = 0.f, sq = 0.f;
#pragma unroll
    for (int m = 0; m < 4; m++) {
        int r = lane + 32 * m;
        const float4* wr = (const float4*)(ew + r * 8);
        float4 wa = wr[0], wb = wr[1];
        float a = eb[r];
        a = fmaf(x0.x, wa.x, a); a = fmaf(x0.y, wa.y, a);
        a = fmaf(x0.z, wa.z, a); a = fmaf(x0.w, wa.w, a);
        a = fmaf(x1.x, wb.x, a); a = fmaf(x1.y, wb.y, a);
        a = fmaf(x1.z, wb.z, a); a = fmaf(x1.w, wb.w, a);
        pre[m] = a;
        sum += a;
        sq = fmaf(a, a, sq);
    }
#pragma unroll
    for (int d = 16; d; d >>= 1) {
        sum += __shfl_xor_sync(FULL, sum, d);
        sq  += __shfl_xor_sync(FULL, sq, d);
    }
    float mean = sum * (1.f / 128.f);
    float rstd = rsqrtf(sq * (1.f / 128.f) - mean * mean + 1e-5f);
    int t = row & (TN - 1);
    float ev[4];
#pragma unroll
    for (int m = 0; m < 4; m++) {
        int r = lane + 32 * m;
        ev[m] = (pre[m] - mean) * rstd * eg[r] + ebt[r] + pe[t * HN + r];
        g_emb[row * HN + r] = ev[m];
    }
    // x-part of input projection
    float pj[8];
#pragma unroll
    for (int j = 0; j < 8; j++) {
        float a = 0.f;
#pragma unroll
        for (int m = 0; m < 4; m++) a = fmaf(ev[m], ipw[j * 256 + lane + 32 * m], a);
        pj[j] = a;
    }
#pragma unroll
    for (int j = 0; j < 8; j++) {
#pragma unroll
        for (int d = 16; d; d >>= 1) pj[j] += __shfl_xor_sync(FULL, pj[j], d);
    }
    if (lane == 0) {
#pragma unroll
        for (int j = 0; j < 8; j++) g_proj[row * 8 + j] = pj[j] + ipb[j];
    }
}

// ---------------------------------------------------------------------------
// VQC helpers. Amp index bits [7:0]; lane = bits[7:3], reg j = bits[2:0].
// Qubit q acts on bit (7-q). RY in tan form (cos factors deferred into C2).
// ---------------------------------------------------------------------------
__device__ __forceinline__ void lane_ry(float (&st)[8], float tq, int lane, int mask) {
    float sg = (lane & mask) ? tq : -tq;
#pragma unroll
    for (int j = 0; j < 8; j++) {
        float o = __shfl_xor_sync(FULL, st[j], mask);
        st[j] = fmaf(sg, o, st[j]);
    }
}
__device__ __forceinline__ void pair_ry(float (&st)[8], float tq, int a, int b) {
    float xx = st[a];
    st[a] = fmaf(-tq, st[b], xx);
    st[b] = fmaf(tq, xx, st[b]);
}

// gate-projection weight row stride: 12 floats (48B) -> conflict-free LDS.128
#define PWS 12

// ---------------------------------------------------------------------------
// Kernel 2: the recurrence. 1 block (128 thr) / batch element, warp w = gate w.
// ---------------------------------------------------------------------------
__global__ __launch_bounds__(128, 7) void k_main(
    const float* __restrict__ ipw,
    const float* __restrict__ ing, const float* __restrict__ inb,
    const float* __restrict__ wqi, const float* __restrict__ wqf,
    const float* __restrict__ wqg, const float* __restrict__ wqo,
    const float* __restrict__ piw, const float* __restrict__ pib,
    const float* __restrict__ pfw, const float* __restrict__ pfb,
    const float* __restrict__ pgw, const float* __restrict__ pgb,
    const float* __restrict__ pow_, const float* __restrict__ pob,
    const float* __restrict__ ong, const float* __restrict__ onb,
    const float* __restrict__ outw, const float* __restrict__ outb,
    float* __restrict__ out) {
    __shared__ float s_t[4][32];           // variational tans per gate
    __shared__ float s_pw[4][HN * PWS];    // gate proj weights, padded rows (48B)
    __shared__ float s_pr[8];              // tanh(proj) pre-LN
    __shared__ float s_g[4][HN];           // gate activations
    __shared__ float s_in2[16];            // 0.5*in_g, 0.5*in_b
    __shared__ float s_ong[HN], s_onb[HN], s_outw[HN];

    int tid = threadIdx.x;
    int w = tid >> 5, lane = tid & 31;
    int b = blockIdx.x;

    for (int i = tid; i < 1024; i += 128) {
        int r = i >> 3, q = i & 7;
        s_pw[0][r * PWS + q] = piw[i];
        s_pw[1][r * PWS + q] = pfw[i];
        s_pw[2][r * PWS + q] = pgw[i];
        s_pw[3][r * PWS + q] = pow_[i];
    }
    // per-warp variational trig: tans into shared, C2 via product-reduce
    const float* wq = (w == 0) ? wqi : (w == 1) ? wqf : (w == 2) ? wqg : wqo;
    float C2;
    {
        float s, cc;
        sincosf(0.5f * wq[lane], &s, &cc);
        s_t[w][lane] = s / cc;
        float p = cc;
#pragma unroll
        for (int d = 16; d; d >>= 1) p *= __shfl_xor_sync(FULL, p, d);
        C2 = p * p;
    }
    if (tid < 8) { s_in2[tid] = 0.5f * ing[tid]; s_in2[8 + tid] = 0.5f * inb[tid]; }
    s_ong[tid] = ong[tid]; s_onb[tid] = onb[tid]; s_outw[tid] = outw[tid];

    const float* pb = (w == 0) ? pib : (w == 1) ? pfb : (w == 2) ? pgb : pob;
    float gb[4];
#pragma unroll
    for (int m = 0; m < 4; m++) gb[m] = pb[lane + 32 * m];
    float ob0 = outb[0];

    // hoisted stage-1 ip_w h-half rows (constant across iterations)
    int j0 = 2 * w;
    float wA[4], wB[4];
#pragma unroll
    for (int m = 0; m < 4; m++) {
        int k = lane + 32 * m;
        wA[m] = ipw[j0 * 256 + 128 + k];
        wB[m] = ipw[(j0 + 1) * 256 + 128 + k];
    }

    // Composed CNOT-block permutation: src_lane + publish selector (constant)
    int l0 = lane & 1, l1 = (lane >> 1) & 1, l2 = (lane >> 2) & 1,
        l3 = (lane >> 3) & 1, l4 = (lane >> 4) & 1;
    int srcL = (l4 << 4) | ((l3 ^ l4) << 3) | ((l2 ^ l3) << 2) |
               ((l1 ^ l2 ^ l3) << 1) | (l0 ^ l1);
    bool pp = (l0 != 0);

    float h[4] = {0.f, 0.f, 0.f, 0.f}, c[4] = {0.f, 0.f, 0.f, 0.f};
    __syncthreads();

    long rowbase = (long)b * TN;

    // pipelined prefetch of the x-projection pair (consumed at stage-1 end)
    float gpv = 0.f;
    if (lane < 2) gpv = g_proj[rowbase * 8 + j0 + lane];

#pragma unroll 1
    for (int t = 0; t < TN; t++) {
        // ---- early prefetch of emb row for this iteration's epilogue warp ----
        float pv[4];
        bool epi = (w == (t & 3));
        if (epi) {
            const float* embp = g_emb + (rowbase + t) * HN;
#pragma unroll
            for (int m = 0; m < 4; m++) pv[m] = embp[lane + 32 * m];
        }

        // ---- stage 1: h-part of proj; 2-value packed reduction ----
        float a0 = 0.f, a1 = 0.f;
#pragma unroll
        for (int m = 0; m < 4; m++) {
            a0 = fmaf(h[m], wA[m], a0);
            a1 = fmaf(h[m], wB[m], a1);
        }
        {
            float v = (lane & 1) ? a0 : a1;
            float o = __shfl_xor_sync(FULL, v, 1);
            if (lane & 1) a1 += o; else a0 += o;
            float r = (lane & 1) ? a1 : a0;
#pragma unroll
            for (int d = 2; d <= 16; d <<= 1) r += __shfl_xor_sync(FULL, r, d);
            if (lane < 2) s_pr[j0 + lane] = tanh_fast(r + gpv);
        }
        __syncthreads();
        // reissue prefetch for next iteration (latency hidden by the VQC)
        if (lane < 2) {
            int tn = (t + 1 < TN) ? (t + 1) : t;
            gpv = g_proj[(rowbase + tn) * 8 + j0 + lane];
        }

        // ---- stage 2: LN over the 8 proj values (warp-uniform) ----
        float pj[8], psum = 0.f;
#pragma unroll
        for (int j = 0; j < 8; j++) { pj[j] = s_pr[j]; psum += pj[j]; }
        float pm = psum * 0.125f;
        float pvv = 0.f;
#pragma unroll
        for (int j = 0; j < 8; j++) { float d = pj[j] - pm; pvv = fmaf(d, d, pvv); }
        float prs = rsqrtf(pvv * 0.125f + 1e-5f);

        // ---- input layer as a product state (zero shuffles) ----
        float st[8];
        float P = 0.0625f;
        float fm5, fp5, fm6, fp6, fm7, fp7;
        {
            float sn, cs, ang;
#define ANG(Q) ang = fmaf((pj[Q] - pm) * prs, s_in2[Q], s_in2[8 + Q]); \
               __sincosf(ang, &sn, &cs);
            ANG(0) P *= (lane & 16) ? (cs + sn) : (cs - sn);
            ANG(1) P *= (lane & 8)  ? (cs + sn) : (cs - sn);
            ANG(2) P *= (lane & 4)  ? (cs + sn) : (cs - sn);
            ANG(3) P *= (lane & 2)  ? (cs + sn) : (cs - sn);
            ANG(4) P *= (lane & 1)  ? (cs + sn) : (cs - sn);
            ANG(5) fm5 = cs - sn; fp5 = cs + sn;
            ANG(6) fm6 = cs - sn; fp6 = cs + sn;
            ANG(7) fm7 = cs - sn; fp7 = cs + sn;
#undef ANG
        }
        {
            float r0 = P * (fm5 * fm6), r1 = P * (fm5 * fp6);
            float r2 = P * (fp5 * fm6), r3 = P * (fp5 * fp6);
            st[0] = r0 * fm7; st[1] = r0 * fp7;
            st[2] = r1 * fm7; st[3] = r1 * fp7;
            st[4] = r2 * fm7; st[5] = r2 * fp7;
            st[6] = r3 * fm7; st[7] = r3 * fp7;
        }

        // ---- variational layers ----
#pragma unroll 1
        for (int l = 0; l < 4; l++) {
            // all 7 CNOTs composed: one indexed shuffle per register
            float n0 = __shfl_sync(FULL, pp ? st[4] : st[0], srcL);
            float n1 = __shfl_sync(FULL, pp ? st[5] : st[1], srcL);
            float n2 = __shfl_sync(FULL, pp ? st[7] : st[3], srcL);
            float n3 = __shfl_sync(FULL, pp ? st[6] : st[2], srcL);
            float n4 = __shfl_sync(FULL, pp ? st[3] : st[7], srcL);
            float n5 = __shfl_sync(FULL, pp ? st[2] : st[6], srcL);
            float n6 = __shfl_sync(FULL, pp ? st[0] : st[4], srcL);
            float n7 = __shfl_sync(FULL, pp ? st[1] : st[5], srcL);
            st[0] = n0; st[1] = n1; st[2] = n2; st[3] = n3;
            st[4] = n4; st[5] = n5; st[6] = n6; st[7] = n7;

            // vectorized tan loads (2 x LDS.128 broadcast)
            float4 ta = *(const float4*)&s_t[w][l * 8];
            float4 tb = *(const float4*)&s_t[w][l * 8 + 4];
            lane_ry(st, ta.x, lane, 16);
            lane_ry(st, ta.y, lane, 8);
            lane_ry(st, ta.z, lane, 4);
            lane_ry(st, ta.w, lane, 2);
            lane_ry(st, tb.x, lane, 1);
            { float tq = tb.y;
              pair_ry(st, tq, 0, 4); pair_ry(st, tq, 1, 5);
              pair_ry(st, tq, 2, 6); pair_ry(st, tq, 3, 7); }
            { float tq = tb.z;
              pair_ry(st, tq, 0, 2); pair_ry(st, tq, 1, 3);
              pair_ry(st, tq, 4, 6); pair_ry(st, tq, 5, 7); }
            { float tq = tb.w;
              pair_ry(st, tq, 0, 1); pair_ry(st, tq, 2, 3);
              pair_ry(st, tq, 4, 5); pair_ry(st, tq, 6, 7); }
        }

        // ---- readout: local Walsh coefficients over registers ----
        float q0 = st[0] * st[0], q1 = st[1] * st[1];
        float q2 = st[2] * st[2], q3 = st[3] * st[3];
        float q4 = st[4] * st[4], q5 = st[5] * st[5];
        float q6 = st[6] * st[6], q7 = st[7] * st[7];
        float e01 = q0 + q1, e23 = q2 + q3, e45 = q4 + q5, e67 = q6 + q7;
        float A = e01 + e23, B = e45 + e67;
        float tot = A + B;
        float z5 = A - B;                                             // qubit5 (reg bit2)
        float z6 = (e01 - e23) + (e45 - e67);                         // qubit6 (reg bit1)
        float z7 = ((q0 - q1) + (q2 - q3)) + ((q4 - q5) + (q6 - q7)); // qubit7 (reg bit0)

        // Walsh-Hadamard butterfly over lanes: lane (1<<(4-q)) ends with z_q
        float wz = tot;
#pragma unroll
        for (int d = 16; d; d >>= 1) {
            float o = __shfl_xor_sync(FULL, wz, d);
            wz = (lane & d) ? (o - wz) : (wz + o);
        }
        // packed 3-value reduction for z5, z6, z7 (9 SHFL instead of 15)
        float Z5, Z6, Z7;
        {
            float v1 = (lane & 1) ? z5 : z7;
            float o1 = __shfl_xor_sync(FULL, v1, 1);
            float o2 = __shfl_xor_sync(FULL, z6, 1);
            if (lane & 1) { z7 += o1; } else { z5 += o1; z6 += o2; }
            float v2 = (lane & 1) ? z7 : ((lane & 2) ? z5 : z6);
            float o3 = __shfl_xor_sync(FULL, v2, 2);
            int m4 = lane & 3;
            float live;
            if (m4 == 0)      { z5 += o3; live = z5; }
            else if (m4 == 1) { z7 += o3; live = z7; }
            else if (m4 == 2) { z6 += o3; live = z6; }
            else live = 0.f;
#pragma unroll
            for (int d = 4; d <= 16; d <<= 1) live += __shfl_xor_sync(FULL, live, d);
            Z5 = __shfl_sync(FULL, live, 0);
            Z7 = __shfl_sync(FULL, live, 1);
            Z6 = __shfl_sync(FULL, live, 2);
        }
        float z[8];
        z[0] = C2 * __shfl_sync(FULL, wz, 16);
        z[1] = C2 * __shfl_sync(FULL, wz, 8);
        z[2] = C2 * __shfl_sync(FULL, wz, 4);
        z[3] = C2 * __shfl_sync(FULL, wz, 2);
        z[4] = C2 * __shfl_sync(FULL, wz, 1);
        z[5] = C2 * Z5;
        z[6] = C2 * Z6;
        z[7] = C2 * Z7;

        // ---- gate projection + activation (padded conflict-free rows) ----
#pragma unroll
        for (int m = 0; m < 4; m++) {
            int r = lane + 32 * m;
            const float* wr = &s_pw[w][r * PWS];
            float4 wa = *(const float4*)wr;
            float4 wb = *(const float4*)(wr + 4);
            float pre = gb[m];
            pre = fmaf(z[0], wa.x, pre); pre = fmaf(z[1], wa.y, pre);
            pre = fmaf(z[2], wa.z, pre); pre = fmaf(z[3], wa.w, pre);
            pre = fmaf(z[4], wb.x, pre); pre = fmaf(z[5], wb.y, pre);
            pre = fmaf(z[6], wb.z, pre); pre = fmaf(z[7], wb.w, pre);
            float act = (w == 2) ? tanh_fast(pre) : sigmoid_fast(pre);
            s_g[w][r] = act;
        }
        __syncthreads();

        // ---- epilogue: all warps update h,c redundantly (regs) ----
#pragma unroll
        for (int m = 0; m < 4; m++) {
            int r = lane + 32 * m;
            float it = s_g[0][r], ft = s_g[1][r], gt = s_g[2][r], ot = s_g[3][r];
            c[m] = fmaf(ft, c[m], it * gt);
            h[m] = ot * tanh_fast(c[m]);
        }
        // output LN + dot: rotate across warps to balance SMSPs
        if (epi) {
            float v[4], sum = 0.f, sq = 0.f;
#pragma unroll
            for (int m = 0; m < 4; m++) {
                v[m] = h[m] + pv[m];
                sum += v[m];
                sq = fmaf(v[m], v[m], sq);
            }
            // packed 2-value reduction (7 SHFL instead of 10)
            {
                float vv = (lane & 1) ? sum : sq;
                float o = __shfl_xor_sync(FULL, vv, 1);
                if (lane & 1) sq += o; else sum += o;
                float r = (lane & 1) ? sq : sum;
#pragma unroll
                for (int d = 2; d <= 16; d <<= 1) r += __shfl_xor_sync(FULL, r, d);
                sum = __shfl_sync(FULL, r, 0);
                sq  = __shfl_sync(FULL, r, 1);
            }
            float mean = sum * (1.f / 128.f);
            float rstd = rsqrtf(sq * (1.f / 128.f) - mean * mean + 1e-5f);
            float acc = 0.f;
#pragma unroll
            for (int m = 0; m < 4; m++) {
                int r = lane + 32 * m;
                float y = (v[m] - mean) * rstd * s_ong[r] + s_onb[r];
                acc = fmaf(y, s_outw[r], acc);
            }
#pragma unroll
            for (int d = 16; d; d >>= 1) acc += __shfl_xor_sync(FULL, acc, d);
            if (lane == 0) out[rowbase + t] = acc + ob0;
        }
    }
}

// ---------------------------------------------------------------------------
// Launch. Input order:
// 0:x 1:pe 2:emb_w 3:emb_b 4:emb_g 5:emb_bt 6:ip_w 7:ip_b 8:in_g 9:in_b
// 10:wq_i 11:wq_f 12:wq_g 13:wq_o 14:pi_w 15:pi_b 16:pf_w 17:pf_b
// 18:pg_w 19:pg_b 20:po_w 21:po_b 22:on_g 23:on_b 24:out_w 25:out_b
// ---------------------------------------------------------------------------
extern "C" void kernel_launch(void* const* d_in, const int* in_sizes, int n_in,
                              void* d_out, int out_size) {
    const float* x     = (const float*)d_in[0];
    const float* pe    = (const float*)d_in[1];
    const float* emb_w = (const float*)d_in[2];
    const float* emb_b = (const float*)d_in[3];
    const float* emb_g = (const float*)d_in[4];
    const float* emb_bt= (const float*)d_in[5];
    const float* ip_w  = (const float*)d_in[6];
    const float* ip_b  = (const float*)d_in[7];
    const float* in_g  = (const float*)d_in[8];
    const float* in_b  = (const float*)d_in[9];
    const float* wq_i  = (const float*)d_in[10];
    const float* wq_f  = (const float*)d_in[11];
    const float* wq_g  = (const float*)d_in[12];
    const float* wq_o  = (const float*)d_in[13];
    const float* pi_w  = (const float*)d_in[14];
    const float* pi_b  = (const float*)d_in[15];
    const float* pf_w  = (const float*)d_in[16];
    const float* pf_b  = (const float*)d_in[17];
    const float* pg_w  = (const float*)d_in[18];
    const float* pg_b  = (const float*)d_in[19];
    const float* po_w  = (const float*)d_in[20];
    const float* po_b  = (const float*)d_in[21];
    const float* on_g  = (const float*)d_in[22];
    const float* on_b  = (const float*)d_in[23];
    const float* out_w = (const float*)d_in[24];
    const float* out_b = (const float*)d_in[25];
    float* out = (float*)d_out;

    k_emb<<<(BN * TN) / 8, 256>>>(x, pe, emb_w, emb_b, emb_g, emb_bt, ip_w, ip_b);
    k_main<<<BN, 128>>>(ip_w, in_g, in_b,
                        wq_i, wq_f, wq_g, wq_o,
                        pi_w, pi_b, pf_w, pf_b, pg_w, pg_b, po_w, po_b,
                        on_g, on_b, out_w, out_b, out);
}

// round 14
// speedup vs baseline: 1.4468x; 1.0173x over previous
#include <cuda_runtime.h>
#include <cuda_fp16.h>

#define BN 1024
#define TN 128
#define HN 128
#define FULL 0xffffffffu

// Scratch (static __device__, no allocation)
__device__ float g_emb[BN * TN * HN];     // 64 MB embedding

// ---------------------------------------------------------------------------
// fast activations (__expf max err ~2ulp)
// ---------------------------------------------------------------------------
__device__ __forceinline__ float tanh_fast(float x) {
    float e = __expf(-2.f * fabsf(x));
    float r = __fdividef(1.f - e, 1.f + e);
    return copysignf(r, x);
}
__device__ __forceinline__ float sigmoid_fast(float x) {
    return __fdividef(1.f, 1.f + __expf(-x));
}

// ---------------------------------------------------------------------------
// VQC helpers. Amp index bits [7:0]; lane = bits[7:3], reg j = bits[2:0].
// Qubit q acts on bit (7-q). RY in tan form (cos factors deferred into C2).
// ---------------------------------------------------------------------------
__device__ __forceinline__ void lane_ry(float (&st)[8], float tq, int lane, int mask) {
    float sg = (lane & mask) ? tq : -tq;
#pragma unroll
    for (int j = 0; j < 8; j++) {
        float o = __shfl_xor_sync(FULL, st[j], mask);
        st[j] = fmaf(sg, o, st[j]);
    }
}
__device__ __forceinline__ void pair_ry(float (&st)[8], float tq, int a, int b) {
    float xx = st[a];
    st[a] = fmaf(-tq, st[b], xx);
    st[b] = fmaf(tq, xx, st[b]);
}

// ---------------------------------------------------------------------------
// Single fused kernel. 1 block (128 thr) / batch element, warp w = gate w.
// Prologue: thread t computes emb row t (LN thread-local) + x-part projection.
// ---------------------------------------------------------------------------
__global__ __launch_bounds__(128, 7) void k_main(
    const float* __restrict__ x, const float* __restrict__ pe,
    const float* __restrict__ ew, const float* __restrict__ eb,
    const float* __restrict__ eg, const float* __restrict__ ebt,
    const float* __restrict__ ipw, const float* __restrict__ ipb,
    const float* __restrict__ ing, const float* __restrict__ inb,
    const float* __restrict__ wqi, const float* __restrict__ wqf,
    const float* __restrict__ wqg, const float* __restrict__ wqo,
    const float* __restrict__ piw, const float* __restrict__ pib,
    const float* __restrict__ pfw, const float* __restrict__ pfb,
    const float* __restrict__ pgw, const float* __restrict__ pgb,
    const float* __restrict__ pow_, const float* __restrict__ pob,
    const float* __restrict__ ong, const float* __restrict__ onb,
    const float* __restrict__ outw, const float* __restrict__ outb,
    float* __restrict__ out) {
    __shared__ float s_t[4][32];            // variational tans per gate
    __shared__ __half s_pwh[4][HN * 8];     // gate proj weights, fp16, 16B/row
    __shared__ float s_proj[TN][8];         // x-part of input projection (+bias)
    __shared__ float s_pr[8];               // tanh(proj) pre-LN (16B-aligned)
    __shared__ float s_z[4][8];             // per-warp z bounce (32B rows)
    __shared__ float s_g[4][HN];            // gate activations
    __shared__ float s_in2[16];             // 0.5*in_g, 0.5*in_b
    __shared__ float s_ong[HN], s_onb[HN], s_outw[HN];

    int tid = threadIdx.x;
    int w = tid >> 5, lane = tid & 31;
    int b = blockIdx.x;
    long rowbase = (long)b * TN;

    // ---- prologue A: shared weight staging ----
    for (int i = tid; i < 1024; i += 128) {
        s_pwh[0][i] = __float2half(piw[i]);
        s_pwh[1][i] = __float2half(pfw[i]);
        s_pwh[2][i] = __float2half(pgw[i]);
        s_pwh[3][i] = __float2half(pow_[i]);
    }
    const float* wq = (w == 0) ? wqi : (w == 1) ? wqf : (w == 2) ? wqg : wqo;
    float C2;
    {
        float s, cc;
        sincosf(0.5f * wq[lane], &s, &cc);
        s_t[w][lane] = s / cc;
        float p = cc;
#pragma unroll
        for (int d = 16; d; d >>= 1) p *= __shfl_xor_sync(FULL, p, d);
        C2 = p * p;
    }
    if (tid < 8) { s_in2[tid] = 0.5f * ing[tid]; s_in2[8 + tid] = 0.5f * inb[tid]; }
    s_ong[tid] = ong[tid]; s_onb[tid] = onb[tid]; s_outw[tid] = outw[tid];

    const float* pb = (w == 0) ? pib : (w == 1) ? pfb : (w == 2) ? pgb : pob;
    float gb[4];
#pragma unroll
    for (int m = 0; m < 4; m++) gb[m] = pb[lane + 32 * m];
    float ob0 = outb[0];

    // hoisted stage-1 ip_w h-half rows (constant across iterations)
    int j0 = 2 * w;
    float wA[4], wB[4];
#pragma unroll
    for (int m = 0; m < 4; m++) {
        int k = lane + 32 * m;
        wA[m] = ipw[j0 * 256 + 128 + k];
        wB[m] = ipw[(j0 + 1) * 256 + 128 + k];
    }

    // ---- prologue B: emb row t (thread-local LN) + x-projection ----
    {
        int t = tid;
        const float* xr = x + (rowbase + t) * 8;
        float4 x0 = *(const float4*)xr;
        float4 x1 = *(const float4*)(xr + 4);
        // pass 1: pre-activation stats
        float sum = 0.f, sq = 0.f;
#pragma unroll 4
        for (int k = 0; k < HN; k++) {
            const float4* wr = (const float4*)(ew + k * 8);
            float4 wa = wr[0], wb = wr[1];
            float a = eb[k];
            a = fmaf(x0.x, wa.x, a); a = fmaf(x0.y, wa.y, a);
            a = fmaf(x0.z, wa.z, a); a = fmaf(x0.w, wa.w, a);
            a = fmaf(x1.x, wb.x, a); a = fmaf(x1.y, wb.y, a);
            a = fmaf(x1.z, wb.z, a); a = fmaf(x1.w, wb.w, a);
            sum += a;
            sq = fmaf(a, a, sq);
        }
        float mean = sum * (1.f / 128.f);
        float rstd = rsqrtf(sq * (1.f / 128.f) - mean * mean + 1e-5f);
        // pass 2: recompute, normalize, emit emb + projection
        float pj[8];
#pragma unroll
        for (int j = 0; j < 8; j++) pj[j] = 0.f;
#pragma unroll 1
        for (int kc = 0; kc < HN / 4; kc++) {
            float e4[4];
            float4 pev = *(const float4*)(pe + t * HN + kc * 4);
            float4 egv = *(const float4*)(eg + kc * 4);
            float4 ebtv = *(const float4*)(ebt + kc * 4);
#pragma unroll
            for (int r4 = 0; r4 < 4; r4++) {
                int k = kc * 4 + r4;
                const float4* wr = (const float4*)(ew + k * 8);
                float4 wa = wr[0], wb = wr[1];
                float a = eb[k];
                a = fmaf(x0.x, wa.x, a); a = fmaf(x0.y, wa.y, a);
                a = fmaf(x0.z, wa.z, a); a = fmaf(x0.w, wa.w, a);
                a = fmaf(x1.x, wb.x, a); a = fmaf(x1.y, wb.y, a);
                a = fmaf(x1.z, wb.z, a); a = fmaf(x1.w, wb.w, a);
                float gval = ((const float*)&egv)[r4];
                float btv = ((const float*)&ebtv)[r4];
                float pv = ((const float*)&pev)[r4];
                e4[r4] = (a - mean) * rstd * gval + btv + pv;
            }
#pragma unroll
            for (int j = 0; j < 8; j++) {
                float4 w4 = *(const float4*)(ipw + j * 256 + kc * 4);
                float acc = pj[j];
                acc = fmaf(e4[0], w4.x, acc); acc = fmaf(e4[1], w4.y, acc);
                acc = fmaf(e4[2], w4.z, acc); acc = fmaf(e4[3], w4.w, acc);
                pj[j] = acc;
            }
            *(float4*)(g_emb + (rowbase + t) * HN + kc * 4) =
                make_float4(e4[0], e4[1], e4[2], e4[3]);
        }
#pragma unroll
        for (int j = 0; j < 8; j++) s_proj[t][j] = pj[j] + ipb[j];
    }

    // Composed CNOT-block permutation: src_lane + publish selector (constant)
    int l0 = lane & 1, l1 = (lane >> 1) & 1, l2 = (lane >> 2) & 1,
        l3 = (lane >> 3) & 1, l4 = (lane >> 4) & 1;
    int srcL = (l4 << 4) | ((l3 ^ l4) << 3) | ((l2 ^ l3) << 2) |
               ((l1 ^ l2 ^ l3) << 1) | (l0 ^ l1);
    bool pp = (l0 != 0);
    // z-bounce slot for this lane (-1 = no store)
    int slot = (lane == 16) ? 0 : (lane == 8) ? 1 : (lane == 4) ? 2 :
               (lane == 2) ? 3 : (lane == 1) ? 4 :
               (lane == 12) ? 5 : (lane == 14) ? 6 : (lane == 13) ? 7 : -1;

    float h[4] = {0.f, 0.f, 0.f, 0.f}, c[4] = {0.f, 0.f, 0.f, 0.f};
    __syncthreads();

#pragma unroll 1
    for (int t = 0; t < TN; t++) {
        // ---- early prefetch of emb row for this iteration's epilogue warp ----
        float pv[4];
        bool epi = (w == (t & 3));
        if (epi) {
            const float* embp = g_emb + (rowbase + t) * HN;
#pragma unroll
            for (int m = 0; m < 4; m++) pv[m] = embp[lane + 32 * m];
        }

        // ---- stage 1: h-part of proj; 2-value packed reduction ----
        float a0 = 0.f, a1 = 0.f;
#pragma unroll
        for (int m = 0; m < 4; m++) {
            a0 = fmaf(h[m], wA[m], a0);
            a1 = fmaf(h[m], wB[m], a1);
        }
        {
            float v = (lane & 1) ? a0 : a1;
            float o = __shfl_xor_sync(FULL, v, 1);
            if (lane & 1) a1 += o; else a0 += o;
            float r = (lane & 1) ? a1 : a0;
#pragma unroll
            for (int d = 2; d <= 16; d <<= 1) r += __shfl_xor_sync(FULL, r, d);
            if (lane < 2) s_pr[j0 + lane] = tanh_fast(r + s_proj[t][j0 + lane]);
        }
        __syncthreads();

        // ---- stage 2: LN over the 8 proj values (uniform float4 loads) ----
        float pj[8], psum = 0.f;
        {
            float4 pra = *(const float4*)&s_pr[0];
            float4 prb = *(const float4*)&s_pr[4];
            pj[0] = pra.x; pj[1] = pra.y; pj[2] = pra.z; pj[3] = pra.w;
            pj[4] = prb.x; pj[5] = prb.y; pj[6] = prb.z; pj[7] = prb.w;
        }
#pragma unroll
        for (int j = 0; j < 8; j++) psum += pj[j];
        float pm = psum * 0.125f;
        float pvv = 0.f;
#pragma unroll
        for (int j = 0; j < 8; j++) { float d = pj[j] - pm; pvv = fmaf(d, d, pvv); }
        float prs = rsqrtf(pvv * 0.125f + 1e-5f);

        // ---- input layer as a product state (zero shuffles) ----
        float st[8];
        float P = 0.0625f;
        float fm5, fp5, fm6, fp6, fm7, fp7;
        {
            float sn, cs, ang;
#define ANG(Q) ang = fmaf((pj[Q] - pm) * prs, s_in2[Q], s_in2[8 + Q]); \
               __sincosf(ang, &sn, &cs);
            ANG(0) P *= (lane & 16) ? (cs + sn) : (cs - sn);
            ANG(1) P *= (lane & 8)  ? (cs + sn) : (cs - sn);
            ANG(2) P *= (lane & 4)  ? (cs + sn) : (cs - sn);
            ANG(3) P *= (lane & 2)  ? (cs + sn) : (cs - sn);
            ANG(4) P *= (lane & 1)  ? (cs + sn) : (cs - sn);
            ANG(5) fm5 = cs - sn; fp5 = cs + sn;
            ANG(6) fm6 = cs - sn; fp6 = cs + sn;
            ANG(7) fm7 = cs - sn; fp7 = cs + sn;
#undef ANG
        }
        {
            float r0 = P * (fm5 * fm6), r1 = P * (fm5 * fp6);
            float r2 = P * (fp5 * fm6), r3 = P * (fp5 * fp6);
            st[0] = r0 * fm7; st[1] = r0 * fp7;
            st[2] = r1 * fm7; st[3] = r1 * fp7;
            st[4] = r2 * fm7; st[5] = r2 * fp7;
            st[6] = r3 * fm7; st[7] = r3 * fp7;
        }

        // ---- variational layers ----
#pragma unroll 1
        for (int l = 0; l < 4; l++) {
            // all 7 CNOTs composed: one indexed shuffle per register
            float n0 = __shfl_sync(FULL, pp ? st[4] : st[0], srcL);
            float n1 = __shfl_sync(FULL, pp ? st[5] : st[1], srcL);
            float n2 = __shfl_sync(FULL, pp ? st[7] : st[3], srcL);
            float n3 = __shfl_sync(FULL, pp ? st[6] : st[2], srcL);
            float n4 = __shfl_sync(FULL, pp ? st[3] : st[7], srcL);
            float n5 = __shfl_sync(FULL, pp ? st[2] : st[6], srcL);
            float n6 = __shfl_sync(FULL, pp ? st[0] : st[4], srcL);
            float n7 = __shfl_sync(FULL, pp ? st[1] : st[5], srcL);
            st[0] = n0; st[1] = n1; st[2] = n2; st[3] = n3;
            st[4] = n4; st[5] = n5; st[6] = n6; st[7] = n7;

            // uniform LDS.128 broadcasts of the layer tans
            float4 ta = *(const float4*)&s_t[w][l * 8];
            float4 tb = *(const float4*)&s_t[w][l * 8 + 4];
            lane_ry(st, ta.x, lane, 16);
            lane_ry(st, ta.y, lane, 8);
            lane_ry(st, ta.z, lane, 4);
            lane_ry(st, ta.w, lane, 2);
            lane_ry(st, tb.x, lane, 1);
            { float tq = tb.y;
              pair_ry(st, tq, 0, 4); pair_ry(st, tq, 1, 5);
              pair_ry(st, tq, 2, 6); pair_ry(st, tq, 3, 7); }
            { float tq = tb.z;
              pair_ry(st, tq, 0, 2); pair_ry(st, tq, 1, 3);
              pair_ry(st, tq, 4, 6); pair_ry(st, tq, 5, 7); }
            { float tq = tb.w;
              pair_ry(st, tq, 0, 1); pair_ry(st, tq, 2, 3);
              pair_ry(st, tq, 4, 5); pair_ry(st, tq, 6, 7); }
        }

        // ---- readout: local Walsh coefficients over registers ----
        float q0 = st[0] * st[0], q1 = st[1] * st[1];
        float q2 = st[2] * st[2], q3 = st[3] * st[3];
        float q4 = st[4] * st[4], q5 = st[5] * st[5];
        float q6 = st[6] * st[6], q7 = st[7] * st[7];
        float e01 = q0 + q1, e23 = q2 + q3, e45 = q4 + q5, e67 = q6 + q7;
        float A = e01 + e23, B = e45 + e67;
        float tot = A + B;
        float z5 = A - B;                                             // qubit5 (reg bit2)
        float z6 = (e01 - e23) + (e45 - e67);                         // qubit6 (reg bit1)
        float z7 = ((q0 - q1) + (q2 - q3)) + ((q4 - q5) + (q6 - q7)); // qubit7 (reg bit0)

        // Walsh-Hadamard butterfly over lanes: lane (1<<(4-q)) ends with z_q
        float wz = tot;
#pragma unroll
        for (int d = 16; d; d >>= 1) {
            float o = __shfl_xor_sync(FULL, wz, d);
            wz = (lane & d) ? (o - wz) : (wz + o);
        }
        // packed 3-value reduction for z5, z6, z7; classes m4={0,1,2} -> {z5,z7,z6}
        float live;
        {
            float v1 = (lane & 1) ? z5 : z7;
            float o1 = __shfl_xor_sync(FULL, v1, 1);
            float o2 = __shfl_xor_sync(FULL, z6, 1);
            if (lane & 1) { z7 += o1; } else { z5 += o1; z6 += o2; }
            float v2 = (lane & 1) ? z7 : ((lane & 2) ? z5 : z6);
            float o3 = __shfl_xor_sync(FULL, v2, 2);
            int m4 = lane & 3;
            if (m4 == 0)      { z5 += o3; live = z5; }
            else if (m4 == 1) { z7 += o3; live = z7; }
            else if (m4 == 2) { z6 += o3; live = z6; }
            else live = 0.f;
#pragma unroll
            for (int d = 4; d <= 16; d <<= 1) live += __shfl_xor_sync(FULL, live, d);
        }
        // ---- z bounce: one STS from 8 designated lanes + 2 uniform LDS.128 ----
        if (slot >= 0) s_z[w][slot] = ((slot >= 5) ? live : wz) * C2;
        __syncwarp();
        float4 za = *(const float4*)&s_z[w][0];
        float4 zb = *(const float4*)&s_z[w][4];

        // ---- gate projection + activation (fp16 weights, 1 LDS.128 per row) ----
#pragma unroll
        for (int m = 0; m < 4; m++) {
            int r = lane + 32 * m;
            uint4 hw = *(const uint4*)&s_pwh[w][r * 8];
            const __half2* hp = (const __half2*)&hw;
            float2 w01 = __half22float2(hp[0]);
            float2 w23 = __half22float2(hp[1]);
            float2 w45 = __half22float2(hp[2]);
            float2 w67 = __half22float2(hp[3]);
            float pre = gb[m];
            pre = fmaf(za.x, w01.x, pre); pre = fmaf(za.y, w01.y, pre);
            pre = fmaf(za.z, w23.x, pre); pre = fmaf(za.w, w23.y, pre);
            pre = fmaf(zb.x, w45.x, pre); pre = fmaf(zb.y, w45.y, pre);
            pre = fmaf(zb.z, w67.x, pre); pre = fmaf(zb.w, w67.y, pre);
            float act = (w == 2) ? tanh_fast(pre) : sigmoid_fast(pre);
            s_g[w][r] = act;
        }
        __syncthreads();

        // ---- epilogue: all warps update h,c redundantly (regs) ----
#pragma unroll
        for (int m = 0; m < 4; m++) {
            int r = lane + 32 * m;
            float it = s_g[0][r], ft = s_g[1][r], gt = s_g[2][r], ot = s_g[3][r];
            c[m] = fmaf(ft, c[m], it * gt);
            h[m] = ot * tanh_fast(c[m]);
        }
        // output LN + dot: rotate across warps to balance SMSPs
        if (epi) {
            float v[4], sum = 0.f, sq = 0.f;
#pragma unroll
            for (int m = 0; m < 4; m++) {
                v[m] = h[m] + pv[m];
                sum += v[m];
                sq = fmaf(v[m], v[m], sq);
            }
            // packed 2-value reduction
            {
                float vv = (lane & 1) ? sum : sq;
                float o = __shfl_xor_sync(FULL, vv, 1);
                if (lane & 1) sq += o; else sum += o;
                float r = (lane & 1) ? sq : sum;
#pragma unroll
                for (int d = 2; d <= 16; d <<= 1) r += __shfl_xor_sync(FULL, r, d);
                sum = __shfl_sync(FULL, r, 0);
                sq  = __shfl_sync(FULL, r, 1);
            }
            float mean = sum * (1.f / 128.f);
            float rstd = rsqrtf(sq * (1.f / 128.f) - mean * mean + 1e-5f);
            float acc = 0.f;
#pragma unroll
            for (int m = 0; m < 4; m++) {
                int r = lane + 32 * m;
                float y = (v[m] - mean) * rstd * s_ong[r] + s_onb[r];
                acc = fmaf(y, s_outw[r], acc);
            }
#pragma unroll
            for (int d = 16; d; d >>= 1) acc += __shfl_xor_sync(FULL, acc, d);
            if (lane == 0) out[rowbase + t] = acc + ob0;
        }
    }
}

// ---------------------------------------------------------------------------
// Launch. Input order:
// 0:x 1:pe 2:emb_w 3:emb_b 4:emb_g 5:emb_bt 6:ip_w 7:ip_b 8:in_g 9:in_b
// 10:wq_i 11:wq_f 12:wq_g 13:wq_o 14:pi_w 15:pi_b 16:pf_w 17:pf_b
// 18:pg_w 19:pg_b 20:po_w 21:po_b 22:on_g 23:on_b 24:out_w 25:out_b
// ---------------------------------------------------------------------------
extern "C" void kernel_launch(void* const* d_in, const int* in_sizes, int n_in,
                              void* d_out, int out_size) {
    const float* x     = (const float*)d_in[0];
    const float* pe    = (const float*)d_in[1];
    const float* emb_w = (const float*)d_in[2];
    const float* emb_b = (const float*)d_in[3];
    const float* emb_g = (const float*)d_in[4];
    const float* emb_bt= (const float*)d_in[5];
    const float* ip_w  = (const float*)d_in[6];
    const float* ip_b  = (const float*)d_in[7];
    const float* in_g  = (const float*)d_in[8];
    const float* in_b  = (const float*)d_in[9];
    const float* wq_i  = (const float*)d_in[10];
    const float* wq_f  = (const float*)d_in[11];
    const float* wq_g  = (const float*)d_in[12];
    const float* wq_o  = (const float*)d_in[13];
    const float* pi_w  = (const float*)d_in[14];
    const float* pi_b  = (const float*)d_in[15];
    const float* pf_w  = (const float*)d_in[16];
    const float* pf_b  = (const float*)d_in[17];
    const float* pg_w  = (const float*)d_in[18];
    const float* pg_b  = (const float*)d_in[19];
    const float* po_w  = (const float*)d_in[20];
    const float* po_b  = (const float*)d_in[21];
    const float* on_g  = (const float*)d_in[22];
    const float* on_b  = (const float*)d_in[23];
    const float* out_w = (const float*)d_in[24];
    const float* out_b = (const float*)d_in[25];
    float* out = (float*)d_out;

    k_main<<<BN, 128>>>(x, pe, emb_w, emb_b, emb_g, emb_bt, ip_w, ip_b,
                        in_g, in_b,
                        wq_i, wq_f, wq_g, wq_o,
                        pi_w, pi_b, pf_w, pf_b, pg_w, pg_b, po_w, po_b,
                        on_g, on_b, out_w, out_b, out);
}